// round 10
// baseline (speedup 1.0000x reference)
#include <cuda_runtime.h>
#include <cuda_bf16.h>
#include <math.h>
#include <stdint.h>

#define B_   2
#define T_   16
#define BT   32
#define NTOK 2304
#define C_   512
#define C3   1536
#define NH   8
#define DH   64
#define EPS  1e-6f

#define M_   (BT * NTOK)   // 73728
#define TM   256
#define TN   256
#define TK   64
#define NCHUNK 24
#define NBM2  (M_ / TM)    // 288
#define NBN   (C3 / TN)    // 6
#define AT_B  32768
#define BT_B  32768
#define STAGES 3
#define STG_B  (AT_B + BT_B)

#if defined(__CUDA_ARCH_FEAT_SM103_ALL) || defined(__CUDA_ARCH_FEAT_SM100_ALL) || \
    (defined(__CUDA_ARCH_SPECIFIC__) && (__CUDA_ARCH_SPECIFIC__ == 1030))
#define HAS_TCGEN05 1
#else
#define HAS_TCGEN05 0
#endif

// ---------------- scratch ----------------
__device__ float g_qkv[(size_t)BT * NTOK * C3];
__device__ __nv_bfloat16 g_At[(size_t)NBM2 * 16 * (AT_B / 2)];
__device__ __nv_bfloat16 g_Bt[(size_t)NBN * 16 * (BT_B / 2)];
__device__ float g_part[BT * 8 * C_];
__device__ float g_partmm[BT * 8];
__device__ float g_xtime[BT * C_];
__device__ float g_mm[BT];
__device__ float g_qkvt[BT * C3];
__device__ float g_tout[BT * C_];
__device__ float g_bias[BT * C3];
__device__ float g_kv[BT * NH * DH * DH];
__device__ float g_ksum[BT * NH * DH];

__device__ __forceinline__ float phi(float x) {
    return x > 0.f ? x + 1.f : expf(x);
}

// ---------------- f32x2 helpers ----------------
__device__ __forceinline__ uint64_t pack2(float lo, float hi) {
    uint64_t r; asm("mov.b64 %0, {%1, %2};" : "=l"(r) : "f"(lo), "f"(hi)); return r;
}
__device__ __forceinline__ float2 unpack2(uint64_t v) {
    float2 f; asm("mov.b64 {%0, %1}, %2;" : "=f"(f.x), "=f"(f.y) : "l"(v)); return f;
}
__device__ __forceinline__ void fma2(uint64_t& d, uint64_t a, uint64_t b) {
#if HAS_TCGEN05
    asm("fma.rn.f32x2 %0, %1, %2, %3;" : "=l"(d) : "l"(a), "l"(b), "l"(d));
#else
    float2 fd = unpack2(d), fa = unpack2(a), fb = unpack2(b);
    fd.x = fmaf(fa.x, fb.x, fd.x);
    fd.y = fmaf(fa.y, fb.y, fd.y);
    d = pack2(fd.x, fd.y);
#endif
}

// ---------------- ptx helpers ----------------
__device__ __forceinline__ uint32_t smem_u32(const void* p) {
    uint32_t a;
    asm("{ .reg .u64 t; cvta.to.shared.u64 t, %1; cvt.u32.u64 %0, t; }" : "=r"(a) : "l"(p));
    return a;
}
static __device__ __forceinline__ uint64_t make_desc(uint32_t addr) {
    const uint64_t base = (uint64_t(2) << 61) | (uint64_t(1) << 46) | (uint64_t(64) << 32) | (uint64_t(1) << 16);
    return base | ((uint64_t)(addr >> 4) & 0x3FFF);
}
__device__ __forceinline__ void mbar_init(uint32_t a, uint32_t cnt) {
    asm volatile("mbarrier.init.shared.b64 [%0], %1;" :: "r"(a), "r"(cnt) : "memory");
}
__device__ __forceinline__ void mbar_inval(uint32_t a) {
    asm volatile("mbarrier.inval.shared.b64 [%0];" :: "r"(a) : "memory");
}
__device__ __forceinline__ void mbar_wait(uint32_t a, uint32_t parity) {
    asm volatile(
        "{\n\t.reg .pred P1;\n\tWL_%=:\n\t"
        "mbarrier.try_wait.parity.acquire.cta.shared::cta.b64 P1, [%0], %1, 0x989680;\n\t"
        "@P1 bra.uni WD_%=;\n\tbra.uni WL_%=;\n\tWD_%=:\n\t}"
        :: "r"(a), "r"(parity) : "memory");
}
__device__ __forceinline__ void mbar_expect_tx(uint32_t a, uint32_t bytes) {
    asm volatile("mbarrier.arrive.expect_tx.shared.b64 _, [%0], %1;"
                 :: "r"(a), "r"(bytes) : "memory");
}
__device__ __forceinline__ void bulk_g2s(uint32_t dst, const void* src, uint32_t bytes, uint32_t mbar) {
    asm volatile("cp.async.bulk.shared::cta.global.mbarrier::complete_tx::bytes [%0], [%1], %2, [%3];"
                 :: "r"(dst), "l"(src), "r"(bytes), "r"(mbar) : "memory");
}

#if HAS_TCGEN05
__device__ __forceinline__ void mma_bf16_ss(uint32_t d, uint64_t ad, uint64_t bd, uint32_t idesc, uint32_t en) {
    asm volatile(
        "{\n\t.reg .pred p;\n\tsetp.ne.u32 p, %4, 0;\n\t"
        "tcgen05.mma.cta_group::1.kind::f16 [%0], %1, %2, %3, {%5, %5, %5, %5}, p;\n\t}"
        :: "r"(d), "l"(ad), "l"(bd), "r"(idesc), "r"(en), "r"(0u) : "memory");
}
__device__ __forceinline__ void tc_commit(uint32_t mbar) {
    asm volatile("tcgen05.commit.cta_group::1.mbarrier::arrive::one.shared::cluster.b64 [%0];"
                 :: "r"(mbar) : "memory");
}
#define TC_ALLOC(sa, n)  asm volatile("tcgen05.alloc.cta_group::1.sync.aligned.shared::cta.b32 [%0], %1;" :: "r"(sa), "r"(n) : "memory")
#define TC_DEALLOC(t, n) asm volatile("tcgen05.dealloc.cta_group::1.sync.aligned.b32 %0, %1;" :: "r"(t), "r"(n))
#define TC_FENCE_AFTER()  asm volatile("tcgen05.fence::after_thread_sync;" ::: "memory")
#define TC_FENCE_BEFORE() asm volatile("tcgen05.fence::before_thread_sync;" ::: "memory")
#define TC_WAIT_LD() asm volatile("tcgen05.wait::ld.sync.aligned;" ::: "memory")
#define LDTM_X32(r, a) \
    asm volatile("tcgen05.ld.sync.aligned.32x32b.x32.b32 " \
        "{%0, %1, %2, %3, %4, %5, %6, %7, %8, %9, %10, %11, %12, %13, %14, %15, " \
        "%16, %17, %18, %19, %20, %21, %22, %23, %24, %25, %26, %27, %28, %29, %30, %31}, [%32];" \
        : "=r"((r)[0]), "=r"((r)[1]), "=r"((r)[2]), "=r"((r)[3]), "=r"((r)[4]), "=r"((r)[5]), "=r"((r)[6]), "=r"((r)[7]), \
          "=r"((r)[8]), "=r"((r)[9]), "=r"((r)[10]), "=r"((r)[11]), "=r"((r)[12]), "=r"((r)[13]), "=r"((r)[14]), "=r"((r)[15]), \
          "=r"((r)[16]), "=r"((r)[17]), "=r"((r)[18]), "=r"((r)[19]), "=r"((r)[20]), "=r"((r)[21]), "=r"((r)[22]), "=r"((r)[23]), \
          "=r"((r)[24]), "=r"((r)[25]), "=r"((r)[26]), "=r"((r)[27]), "=r"((r)[28]), "=r"((r)[29]), "=r"((r)[30]), "=r"((r)[31]) \
        : "r"(a))
#endif

// ---------------- K1: partial frame sums ----------------
__global__ void k1_partial(const float* __restrict__ x, const float* __restrict__ motion) {
    int bt = blockIdx.x, chunk = blockIdx.y;
    int c = threadIdx.x;
    const int RPC = NTOK / 8;
    int n0 = chunk * RPC;
    const float* xp = x + ((size_t)(bt * NTOK + n0)) * C_ + c;
    float s = 0.f;
    for (int r = 0; r < RPC; ++r) s += xp[(size_t)r * C_];
    g_part[(bt * 8 + chunk) * C_ + c] = s;

    __shared__ float sm[512];
    float m = 0.f;
    for (int r = c; r < RPC; r += 512) m += motion[bt * NTOK + n0 + r];
    sm[c] = m;
    __syncthreads();
    for (int off = 256; off > 0; off >>= 1) {
        if (c < off) sm[c] += sm[c + off];
        __syncthreads();
    }
    if (c == 0) g_partmm[bt * 8 + chunk] = sm[0];
}

// ---------------- K2 ----------------
__global__ void k2_final(const float* __restrict__ temb) {
    int bt = blockIdx.x, c = threadIdx.x;
    float s = 0.f;
    for (int j = 0; j < 8; ++j) s += g_part[(bt * 8 + j) * C_ + c];
    g_xtime[bt * C_ + c] = s * (1.f / NTOK) + temb[c];
    if (c == 0) {
        float m = 0.f;
        for (int j = 0; j < 8; ++j) m += g_partmm[bt * 8 + j];
        g_mm[bt] = m * (1.f / NTOK);
    }
}

// ---------------- K3: small vec-mat ----------------
__global__ void k3_vecmat(const float* __restrict__ W, int mode) {
    int bt = blockIdx.x;
    int col = blockIdx.y * 256 + threadIdx.x;
    __shared__ float v[C_];
    for (int i = threadIdx.x; i < C_; i += 256) v[i] = g_xtime[bt * C_ + i];
    __syncthreads();
    float s = 0.f;
    #pragma unroll 8
    for (int c = 0; c < C_; ++c) s += v[c] * W[(size_t)c * C3 + col];
    float* dst = mode ? g_bias : g_qkvt;
    dst[bt * C3 + col] = s;
}

// ---------------- K4: temporal linear attention ----------------
__global__ void k4_temporal() {
    int b = blockIdx.x, h = blockIdx.y, e = threadIdx.x;
    __shared__ float q[T_][DH], k[T_][DH], v[T_][DH];
    __shared__ float kvs[DH][DH + 1], ks[DH], mw[T_];
    for (int t = 0; t < T_; ++t) {
        int base = (b * T_ + t) * C3 + h * DH + e;
        q[t][e] = g_qkvt[base];
        k[t][e] = g_qkvt[base + C_];
        v[t][e] = g_qkvt[base + 2 * C_];
    }
    if (e < T_) mw[e] = 1.f + tanhf(g_mm[b * T_ + e]);
    __syncthreads();
    for (int t = 0; t < T_; ++t) {
        q[t][e] = phi(q[t][e]) * mw[t];
        k[t][e] = phi(k[t][e]);
    }
    __syncthreads();
    {
        float s = 0.f;
        for (int t = 0; t < T_; ++t) s += k[t][e];
        ks[e] = s;
    }
    for (int d = 0; d < DH; ++d) {
        float s = 0.f;
        for (int t = 0; t < T_; ++t) s += k[t][d] * v[t][e];
        kvs[d][e] = s;
    }
    __syncthreads();
    for (int t = 0; t < T_; ++t) {
        float den = 0.f, o = 0.f;
        #pragma unroll
        for (int d = 0; d < DH; ++d) {
            float qd = q[t][d];
            den += qd * ks[d];
            o   += qd * kvs[d][e];
        }
        float z = 1.f / (den + EPS);
        g_tout[(b * T_ + t) * C_ + h * DH + e] = o * z;
    }
}

// ---------------- K5 prep ----------------
__global__ void k5_prep(const float* __restrict__ temb) {
    int bt = blockIdx.x, c = threadIdx.x;
    g_xtime[bt * C_ + c] = temb[c] + g_tout[bt * C_ + c];
}

// ---------------- KA: pre-swizzled 256-row tile-contiguous split-A ----------------
__global__ void kA_split(const float* __restrict__ x) {
    size_t idx = (size_t)blockIdx.x * 256 + threadIdx.x;
    size_t row = idx >> 7;
    int q = (int)(idx & 127);
    float4 v = *(const float4*)(x + (row << 9) + q * 4);
    float f[4] = {v.x, v.y, v.z, v.w};
    uint32_t ph[2], pl[2];
    #pragma unroll
    for (int p = 0; p < 2; ++p) {
        __nv_bfloat16 h0 = __float2bfloat16_rn(f[2 * p]);
        __nv_bfloat16 h1 = __float2bfloat16_rn(f[2 * p + 1]);
        __nv_bfloat16 l0 = __float2bfloat16_rn(f[2 * p] - __bfloat162float(h0));
        __nv_bfloat16 l1 = __float2bfloat16_rn(f[2 * p + 1] - __bfloat162float(h1));
        ph[p] = (uint32_t)__bfloat16_as_ushort(h0) | ((uint32_t)__bfloat16_as_ushort(h1) << 16);
        pl[p] = (uint32_t)__bfloat16_as_ushort(l0) | ((uint32_t)__bfloat16_as_ushort(l1) << 16);
    }
    uint2 hv = {ph[0], ph[1]}, lv = {pl[0], pl[1]};

    int bm2 = (int)(row >> 8);
    int lr  = (int)(row & 255);
    int ch  = q >> 4;
    uint32_t off = (uint32_t)lr * 128 + (uint32_t)(q & 15) * 8;
    uint32_t so = off ^ ((off >> 3) & 0x70);
    char* hiDst = (char*)g_At + ((size_t)(bm2 * 16 + ch)) * AT_B + so;
    *(uint2*)hiDst = hv;
    *(uint2*)(hiDst + 8 * AT_B) = lv;
}

// ---------------- KB: pre-swizzled tile-contiguous split-B ----------------
__global__ void kB_build(const float* __restrict__ W) {
    int n = blockIdx.x * 256 + threadIdx.x;
    int k = blockIdx.y;
    float w = W[(size_t)k * C3 + n];
    __nv_bfloat16 hi = __float2bfloat16_rn(w);
    __nv_bfloat16 lo = __float2bfloat16_rn(w - __bfloat162float(hi));
    int bn = n >> 8, rt = n & 255, ch = k >> 6, col = k & 63;
    uint32_t off = (uint32_t)rt * 128 + (uint32_t)col * 2;
    uint32_t so = off ^ ((off >> 3) & 0x70);
    char* dst = (char*)g_Bt + ((size_t)(bn * 16 + ch)) * BT_B + so;
    *(__nv_bfloat16*)dst = hi;
    *(__nv_bfloat16*)(dst + 8 * BT_B) = lo;
}

// ---------------- K6: 3-stage bulk-async tcgen05 bf16 GEMM, 256x256 tile ----------------
#define SM_TPTR 196608
#define SM_FULL 196616
#define SM_DONE 196640
#define SM_SZ   196664

__global__ void __launch_bounds__(256, 1) k6_mma() {
#if HAS_TCGEN05
    extern __shared__ char smem[];
    uint32_t sb = smem_u32(smem);
    int tid = threadIdx.x;
    int bn = blockIdx.x, bm2 = blockIdx.y;
    int rowBase = bm2 * TM, colBase = bn * TN;

    if (tid < 32) TC_ALLOC(sb + SM_TPTR, 512);
    if (tid == 0) {
        #pragma unroll
        for (int s = 0; s < STAGES; ++s) {
            mbar_init(sb + SM_FULL + 8 * s, 1);
            mbar_init(sb + SM_DONE + 8 * s, 1);
        }
    }
    __syncthreads();
    uint32_t tmem;
    asm volatile("ld.shared.b32 %0, [%1];" : "=r"(tmem) : "r"(sb + SM_TPTR));

    const uint32_t idesc = (1u << 4) | (1u << 7) | (1u << 10) | (16u << 17) | (8u << 24);

    if (tid == 0) {
        const char* Abase = (const char*)g_At + (size_t)bm2 * 16 * AT_B;
        const char* Bbase = (const char*)g_Bt + (size_t)bn * 16 * BT_B;

        #pragma unroll
        for (int p = 0; p < 2; ++p) {
            uint32_t fullb = sb + SM_FULL + 8 * p;
            mbar_expect_tx(fullb, STG_B);
            bulk_g2s(sb + (uint32_t)p * STG_B,        Abase + (size_t)p * AT_B, AT_B, fullb);
            bulk_g2s(sb + (uint32_t)p * STG_B + AT_B, Bbase + (size_t)p * BT_B, BT_B, fullb);
        }

        for (int c = 0; c < NCHUNK; ++c) {
            int s = c % 3;
            mbar_wait(sb + SM_FULL + 8 * s, (c / 3) & 1);

            uint64_t ad0 = make_desc(sb + (uint32_t)s * STG_B);
            uint64_t ad1 = ad0 + 1024;
            uint64_t bd0 = make_desc(sb + (uint32_t)s * STG_B + AT_B);
            uint64_t bd1 = bd0 + 1024;
            #pragma unroll
            for (int ks = 0; ks < 4; ++ks) {
                uint32_t en = (c > 0 || ks > 0) ? 1u : 0u;
                mma_bf16_ss(tmem,       ad0 + 2 * ks, bd0 + 2 * ks, idesc, en);
                mma_bf16_ss(tmem + 128, ad0 + 2 * ks, bd1 + 2 * ks, idesc, en);
                mma_bf16_ss(tmem + 256, ad1 + 2 * ks, bd0 + 2 * ks, idesc, en);
                mma_bf16_ss(tmem + 384, ad1 + 2 * ks, bd1 + 2 * ks, idesc, en);
            }
            tc_commit(sb + SM_DONE + 8 * s);

            int pf = c + 2;
            if (pf < NCHUNK) {
                int sp = pf % 3;
                if (pf >= 3) mbar_wait(sb + SM_DONE + 8 * sp, ((pf - 3) / 3) & 1);
                int at = pf & 15;
                int btile = (pf < 8) ? pf : (pf - 8);
                uint32_t fullb = sb + SM_FULL + 8 * sp;
                mbar_expect_tx(fullb, STG_B);
                bulk_g2s(sb + (uint32_t)sp * STG_B,        Abase + (size_t)at * AT_B, AT_B, fullb);
                bulk_g2s(sb + (uint32_t)sp * STG_B + AT_B, Bbase + (size_t)btile * BT_B, BT_B, fullb);
            }
        }
        mbar_wait(sb + SM_DONE + 8 * 2, 1);
    }
    __syncthreads();
    TC_FENCE_AFTER();

    // epilogue: 8 warps; w 0-3 -> col half 0 (tmem 0-255), w 4-7 -> col half 1 (tmem 256-511)
    int lane = tid & 31, w = tid >> 5;
    int wi = w & 3, mh = w >> 2;
    size_t orow = (size_t)(rowBase + mh * 128 + wi * 32 + lane) * C3 + colBase;
    // NOTE: mh here selects M-half via tmem col offset 256 and row offset 128 consistently
    #pragma unroll
    for (int nb = 0; nb < 2; ++nb) {
        for (int b = 0; b < 4; ++b) {
            uint32_t r[32];
            LDTM_X32(r, tmem + mh * 256 + nb * 128 + b * 32);
            TC_WAIT_LD();
            int cb = nb * 128 + b * 32;
            #pragma unroll
            for (int j = 0; j < 32; j += 4) {
                float4 o;
                o.x = __uint_as_float(r[j + 0]);
                o.y = __uint_as_float(r[j + 1]);
                o.z = __uint_as_float(r[j + 2]);
                o.w = __uint_as_float(r[j + 3]);
                *(float4*)(g_qkv + orow + cb + j) = o;
            }
        }
    }
    TC_FENCE_BEFORE();
    __syncthreads();
    if (tid == 0) {
        #pragma unroll
        for (int s = 0; s < STAGES; ++s) {
            mbar_inval(sb + SM_FULL + 8 * s);
            mbar_inval(sb + SM_DONE + 8 * s);
        }
    }
    __syncthreads();
    if (tid < 32) TC_DEALLOC(tmem, 512);
#else
    // Fallback for the compute_103 PTX pass (never executed on GB300).
    int tid = threadIdx.x;
    int bn = blockIdx.x, bm2 = blockIdx.y;
    int rowBase = bm2 * TM, colBase = bn * TN;
    for (int e = tid; e < TM * TN; e += 256) {
        int i = e / TN, j = e % TN;
        float s = 0.f;
        for (int kk = 0; kk < NCHUNK * TK; ++kk) {
            int c = kk >> 6, col = kk & 63;
            int at = c & 15;
            int btile = (c < 8) ? c : (c - 8);
            uint32_t ao = (uint32_t)i * 128 + col * 2; ao ^= ((ao >> 3) & 0x70);
            uint32_t bo = (uint32_t)j * 128 + col * 2; bo ^= ((bo >> 3) & 0x70);
            float a = __bfloat162float(*(const __nv_bfloat16*)((const char*)g_At + ((size_t)(bm2 * 16 + at)) * AT_B + ao));
            float b = __bfloat162float(*(const __nv_bfloat16*)((const char*)g_Bt + ((size_t)(bn * 16 + btile)) * BT_B + bo));
            s += a * b;
        }
        g_qkv[(size_t)(rowBase + i) * C3 + colBase + j] = s;
    }
#endif
}

// ---------------- K7: kv = phi(k+bias)^T (v+bias), ksum; FFMA2 ----------------
__global__ __launch_bounds__(256) void k7_kv() {
    int bt = blockIdx.x, h = blockIdx.y;
    int t = threadIdx.x;
    int d = t >> 2;                 // 0..63
    int esub = t & 3;               // e range: esub*16 .. +15
    __shared__ __align__(16) float ks[32][DH], vs[32][DH];
    uint64_t acc2[8];
    #pragma unroll
    for (int j = 0; j < 8; ++j) acc2[j] = pack2(0.f, 0.f);
    float accS = 0.f;

    const float* base = g_qkv + (size_t)(bt * NTOK) * C3 + h * DH;
    int lrow = t >> 3;              // 0..31
    int lc = (t & 7) * 8;
    float4 bk0 = *(const float4*)(g_bias + bt * C3 + C_ + h * DH + lc);
    float4 bk1 = *(const float4*)(g_bias + bt * C3 + C_ + h * DH + lc + 4);
    float4 bv0 = *(const float4*)(g_bias + bt * C3 + 2 * C_ + h * DH + lc);
    float4 bv1 = *(const float4*)(g_bias + bt * C3 + 2 * C_ + h * DH + lc + 4);

    for (int n0 = 0; n0 < NTOK; n0 += 32) {
        const float* rp = base + (size_t)(n0 + lrow) * C3;
        float4 k0 = *(const float4*)(rp + C_ + lc);
        float4 k1 = *(const float4*)(rp + C_ + lc + 4);
        float4 v0 = *(const float4*)(rp + 2 * C_ + lc);
        float4 v1 = *(const float4*)(rp + 2 * C_ + lc + 4);
        ks[lrow][lc + 0] = phi(k0.x + bk0.x);
        ks[lrow][lc + 1] = phi(k0.y + bk0.y);
        ks[lrow][lc + 2] = phi(k0.z + bk0.z);
        ks[lrow][lc + 3] = phi(k0.w + bk0.w);
        ks[lrow][lc + 4] = phi(k1.x + bk1.x);
        ks[lrow][lc + 5] = phi(k1.y + bk1.y);
        ks[lrow][lc + 6] = phi(k1.z + bk1.z);
        ks[lrow][lc + 7] = phi(k1.w + bk1.w);
        float4 w0 = {v0.x + bv0.x, v0.y + bv0.y, v0.z + bv0.z, v0.w + bv0.w};
        float4 w1 = {v1.x + bv1.x, v1.y + bv1.y, v1.z + bv1.z, v1.w + bv1.w};
        *(float4*)(&vs[lrow][lc])     = w0;
        *(float4*)(&vs[lrow][lc + 4]) = w1;
        __syncthreads();
        #pragma unroll
        for (int r = 0; r < 32; ++r) {
            float pk = ks[r][d];
            uint64_t pk2 = pack2(pk, pk);
            float4 a0 = *(const float4*)(&vs[r][esub * 16]);
            float4 a1 = *(const float4*)(&vs[r][esub * 16 + 4]);
            float4 a2 = *(const float4*)(&vs[r][esub * 16 + 8]);
            float4 a3 = *(const float4*)(&vs[r][esub * 16 + 12]);
            fma2(acc2[0], pk2, pack2(a0.x, a0.y));
            fma2(acc2[1], pk2, pack2(a0.z, a0.w));
            fma2(acc2[2], pk2, pack2(a1.x, a1.y));
            fma2(acc2[3], pk2, pack2(a1.z, a1.w));
            fma2(acc2[4], pk2, pack2(a2.x, a2.y));
            fma2(acc2[5], pk2, pack2(a2.z, a2.w));
            fma2(acc2[6], pk2, pack2(a3.x, a3.y));
            fma2(acc2[7], pk2, pack2(a3.z, a3.w));
            accS += pk;
        }
        __syncthreads();
    }
    float* kvout = g_kv + ((size_t)(bt * NH + h) * DH + d) * DH + esub * 16;
    #pragma unroll
    for (int j = 0; j < 4; ++j) {
        float2 p0 = unpack2(acc2[2 * j]);
        float2 p1 = unpack2(acc2[2 * j + 1]);
        float4 o = {p0.x, p0.y, p1.x, p1.y};
        *(float4*)(kvout + 4 * j) = o;
    }
    if (esub == 0) g_ksum[(bt * NH + h) * DH + d] = accS;
}

// ---------------- K8: out = (phi(q+bias)*mw) @ kv / den; FFMA2, kv in regs ----------------
__global__ __launch_bounds__(256) void k8_apply(const float* __restrict__ motion,
                                                float* __restrict__ out) {
    int bt = blockIdx.x, h = blockIdx.y, chunk = blockIdx.z;
    int t = threadIdx.x;
    int sub = t >> 6, e = t & 63;
    int lane = t & 31, half = (t >> 5) & 1;
    __shared__ __align__(8) float qs[4][DH];
    __shared__ float dpar[4][2];

    uint64_t kvreg2[DH / 2];
    const float* kvg = g_kv + (size_t)(bt * NH + h) * DH * DH;
    #pragma unroll
    for (int dp = 0; dp < DH / 2; ++dp)
        kvreg2[dp] = pack2(kvg[(2 * dp) * DH + e], kvg[(2 * dp + 1) * DH + e]);
    float kse = g_ksum[(bt * NH + h) * DH + e];
    float bq = g_bias[bt * C3 + h * DH + e];

    int n0 = chunk * 96;
    for (int g = 0; g < 96; g += 4) {
        int n = n0 + g + sub;
        float raw = g_qkv[(size_t)(bt * NTOK + n) * C3 + h * DH + e] + bq;
        float mm = motion[bt * NTOK + n];
        float th;
        asm("tanh.approx.f32 %0, %1;" : "=f"(th) : "f"(mm));
        float qv = phi(raw) * (1.f + th);
        qs[sub][e] = qv;
        float dp = qv * kse;
        #pragma unroll
        for (int off = 16; off > 0; off >>= 1)
            dp += __shfl_xor_sync(0xffffffffu, dp, off);
        if (lane == 0) dpar[sub][half] = dp;
        __syncthreads();
        float den = dpar[sub][0] + dpar[sub][1];
        uint64_t o2 = pack2(0.f, 0.f);
        #pragma unroll
        for (int dpp = 0; dpp < DH / 2; ++dpp) {
            uint64_t q2 = *(const uint64_t*)(&qs[sub][2 * dpp]);
            fma2(o2, q2, kvreg2[dpp]);
        }
        float2 of = unpack2(o2);
        float o = of.x + of.y;
        out[(size_t)(bt * NTOK + n) * C_ + h * DH + e] = o / (den + EPS);
        __syncthreads();
    }
}

// ---------------- launch ----------------
extern "C" void kernel_launch(void* const* d_in, const int* in_sizes, int n_in,
                              void* d_out, int out_size) {
    const float* x      = (const float*)d_in[0];
    const float* motion = (const float*)d_in[1];
    const float* W      = (const float*)d_in[2];
    const float* temb   = (const float*)d_in[3];
    float* out = (float*)d_out;

    cudaFuncSetAttribute(k6_mma, cudaFuncAttributeMaxDynamicSharedMemorySize, SM_SZ);

    kA_split<<<(int)(((size_t)M_ * 128) / 256), 256>>>(x);
    kB_build<<<dim3(C3 / 256, C_), 256>>>(W);
    k1_partial<<<dim3(BT, 8), 512>>>(x, motion);
    k6_mma<<<dim3(NBN, NBM2), 256, SM_SZ>>>();      // profile slot idx 3
    k2_final<<<BT, 512>>>(temb);
    k3_vecmat<<<dim3(BT, 6), 256>>>(W, 0);
    k4_temporal<<<dim3(B_, NH), 64>>>();
    k5_prep<<<BT, 512>>>(temb);
    k3_vecmat<<<dim3(BT, 6), 256>>>(W, 1);
    k7_kv<<<dim3(BT, NH), 256>>>();
    k8_apply<<<dim3(BT, NH, NTOK / 96), 256>>>(motion, out);
}

// round 11
// speedup vs baseline: 1.0382x; 1.0382x over previous
#include <cuda_runtime.h>
#include <cuda_bf16.h>
#include <math.h>
#include <stdint.h>

#define B_   2
#define T_   16
#define BT   32
#define NTOK 2304
#define C_   512
#define C3   1536
#define NH   8
#define DH   64
#define EPS  1e-6f

#define M_   (BT * NTOK)   // 73728
#define TM   256
#define TN   256
#define TK   64
#define NCHUNK 24
#define NBM2  (M_ / TM)    // 288
#define NBN   (C3 / TN)    // 6
#define AT_B  32768
#define BT_B  32768
#define STAGES 3
#define STG_B  (AT_B + BT_B)
#define KPART 4
#define TOKP  (NTOK / KPART)   // 576

#if defined(__CUDA_ARCH_FEAT_SM103_ALL) || defined(__CUDA_ARCH_FEAT_SM100_ALL) || \
    (defined(__CUDA_ARCH_SPECIFIC__) && (__CUDA_ARCH_SPECIFIC__ == 1030))
#define HAS_TCGEN05 1
#else
#define HAS_TCGEN05 0
#endif

// ---------------- scratch ----------------
__device__ float g_qkv[(size_t)BT * NTOK * C3];
__device__ __nv_bfloat16 g_At[(size_t)NBM2 * 16 * (AT_B / 2)];
__device__ __nv_bfloat16 g_Bt[(size_t)NBN * 16 * (BT_B / 2)];
__device__ float g_part[BT * 8 * C_];
__device__ float g_partmm[BT * 8];
__device__ float g_xtime[BT * C_];
__device__ float g_mm[BT];
__device__ float g_qkvt[BT * C3];
__device__ float g_tout[BT * C_];
__device__ float g_bias[BT * C3];
__device__ float g_kv[BT * NH * DH * DH];
__device__ float g_ksum[BT * NH * DH];
__device__ float g_kvp[(size_t)BT * NH * KPART * DH * DH];   // 16.8 MB partials
__device__ float g_ksump[BT * NH * KPART * DH];

__device__ __forceinline__ float phi(float x) {
    return x > 0.f ? x + 1.f : expf(x);
}

// ---------------- f32x2 helpers ----------------
__device__ __forceinline__ uint64_t pack2(float lo, float hi) {
    uint64_t r; asm("mov.b64 %0, {%1, %2};" : "=l"(r) : "f"(lo), "f"(hi)); return r;
}
__device__ __forceinline__ float2 unpack2(uint64_t v) {
    float2 f; asm("mov.b64 {%0, %1}, %2;" : "=f"(f.x), "=f"(f.y) : "l"(v)); return f;
}
__device__ __forceinline__ void fma2(uint64_t& d, uint64_t a, uint64_t b) {
#if HAS_TCGEN05
    asm("fma.rn.f32x2 %0, %1, %2, %3;" : "=l"(d) : "l"(a), "l"(b), "l"(d));
#else
    float2 fd = unpack2(d), fa = unpack2(a), fb = unpack2(b);
    fd.x = fmaf(fa.x, fb.x, fd.x);
    fd.y = fmaf(fa.y, fb.y, fd.y);
    d = pack2(fd.x, fd.y);
#endif
}

// ---------------- ptx helpers ----------------
__device__ __forceinline__ uint32_t smem_u32(const void* p) {
    uint32_t a;
    asm("{ .reg .u64 t; cvta.to.shared.u64 t, %1; cvt.u32.u64 %0, t; }" : "=r"(a) : "l"(p));
    return a;
}
static __device__ __forceinline__ uint64_t make_desc(uint32_t addr) {
    const uint64_t base = (uint64_t(2) << 61) | (uint64_t(1) << 46) | (uint64_t(64) << 32) | (uint64_t(1) << 16);
    return base | ((uint64_t)(addr >> 4) & 0x3FFF);
}
__device__ __forceinline__ void mbar_init(uint32_t a, uint32_t cnt) {
    asm volatile("mbarrier.init.shared.b64 [%0], %1;" :: "r"(a), "r"(cnt) : "memory");
}
__device__ __forceinline__ void mbar_inval(uint32_t a) {
    asm volatile("mbarrier.inval.shared.b64 [%0];" :: "r"(a) : "memory");
}
__device__ __forceinline__ void mbar_wait(uint32_t a, uint32_t parity) {
    asm volatile(
        "{\n\t.reg .pred P1;\n\tWL_%=:\n\t"
        "mbarrier.try_wait.parity.acquire.cta.shared::cta.b64 P1, [%0], %1, 0x989680;\n\t"
        "@P1 bra.uni WD_%=;\n\tbra.uni WL_%=;\n\tWD_%=:\n\t}"
        :: "r"(a), "r"(parity) : "memory");
}
__device__ __forceinline__ void mbar_expect_tx(uint32_t a, uint32_t bytes) {
    asm volatile("mbarrier.arrive.expect_tx.shared.b64 _, [%0], %1;"
                 :: "r"(a), "r"(bytes) : "memory");
}
__device__ __forceinline__ void bulk_g2s(uint32_t dst, const void* src, uint32_t bytes, uint32_t mbar) {
    asm volatile("cp.async.bulk.shared::cta.global.mbarrier::complete_tx::bytes [%0], [%1], %2, [%3];"
                 :: "r"(dst), "l"(src), "r"(bytes), "r"(mbar) : "memory");
}

#if HAS_TCGEN05
__device__ __forceinline__ void mma_bf16_ss(uint32_t d, uint64_t ad, uint64_t bd, uint32_t idesc, uint32_t en) {
    asm volatile(
        "{\n\t.reg .pred p;\n\tsetp.ne.u32 p, %4, 0;\n\t"
        "tcgen05.mma.cta_group::1.kind::f16 [%0], %1, %2, %3, {%5, %5, %5, %5}, p;\n\t}"
        :: "r"(d), "l"(ad), "l"(bd), "r"(idesc), "r"(en), "r"(0u) : "memory");
}
__device__ __forceinline__ void tc_commit(uint32_t mbar) {
    asm volatile("tcgen05.commit.cta_group::1.mbarrier::arrive::one.shared::cluster.b64 [%0];"
                 :: "r"(mbar) : "memory");
}
#define TC_ALLOC(sa, n)  asm volatile("tcgen05.alloc.cta_group::1.sync.aligned.shared::cta.b32 [%0], %1;" :: "r"(sa), "r"(n) : "memory")
#define TC_DEALLOC(t, n) asm volatile("tcgen05.dealloc.cta_group::1.sync.aligned.b32 %0, %1;" :: "r"(t), "r"(n))
#define TC_FENCE_AFTER()  asm volatile("tcgen05.fence::after_thread_sync;" ::: "memory")
#define TC_FENCE_BEFORE() asm volatile("tcgen05.fence::before_thread_sync;" ::: "memory")
#define TC_WAIT_LD() asm volatile("tcgen05.wait::ld.sync.aligned;" ::: "memory")
#define LDTM_X32(r, a) \
    asm volatile("tcgen05.ld.sync.aligned.32x32b.x32.b32 " \
        "{%0, %1, %2, %3, %4, %5, %6, %7, %8, %9, %10, %11, %12, %13, %14, %15, " \
        "%16, %17, %18, %19, %20, %21, %22, %23, %24, %25, %26, %27, %28, %29, %30, %31}, [%32];" \
        : "=r"((r)[0]), "=r"((r)[1]), "=r"((r)[2]), "=r"((r)[3]), "=r"((r)[4]), "=r"((r)[5]), "=r"((r)[6]), "=r"((r)[7]), \
          "=r"((r)[8]), "=r"((r)[9]), "=r"((r)[10]), "=r"((r)[11]), "=r"((r)[12]), "=r"((r)[13]), "=r"((r)[14]), "=r"((r)[15]), \
          "=r"((r)[16]), "=r"((r)[17]), "=r"((r)[18]), "=r"((r)[19]), "=r"((r)[20]), "=r"((r)[21]), "=r"((r)[22]), "=r"((r)[23]), \
          "=r"((r)[24]), "=r"((r)[25]), "=r"((r)[26]), "=r"((r)[27]), "=r"((r)[28]), "=r"((r)[29]), "=r"((r)[30]), "=r"((r)[31]) \
        : "r"(a))
#endif

// ---------------- K1 ----------------
__global__ void k1_partial(const float* __restrict__ x, const float* __restrict__ motion) {
    int bt = blockIdx.x, chunk = blockIdx.y;
    int c = threadIdx.x;
    const int RPC = NTOK / 8;
    int n0 = chunk * RPC;
    const float* xp = x + ((size_t)(bt * NTOK + n0)) * C_ + c;
    float s = 0.f;
    for (int r = 0; r < RPC; ++r) s += xp[(size_t)r * C_];
    g_part[(bt * 8 + chunk) * C_ + c] = s;

    __shared__ float sm[512];
    float m = 0.f;
    for (int r = c; r < RPC; r += 512) m += motion[bt * NTOK + n0 + r];
    sm[c] = m;
    __syncthreads();
    for (int off = 256; off > 0; off >>= 1) {
        if (c < off) sm[c] += sm[c + off];
        __syncthreads();
    }
    if (c == 0) g_partmm[bt * 8 + chunk] = sm[0];
}

// ---------------- K2 ----------------
__global__ void k2_final(const float* __restrict__ temb) {
    int bt = blockIdx.x, c = threadIdx.x;
    float s = 0.f;
    for (int j = 0; j < 8; ++j) s += g_part[(bt * 8 + j) * C_ + c];
    g_xtime[bt * C_ + c] = s * (1.f / NTOK) + temb[c];
    if (c == 0) {
        float m = 0.f;
        for (int j = 0; j < 8; ++j) m += g_partmm[bt * 8 + j];
        g_mm[bt] = m * (1.f / NTOK);
    }
}

// ---------------- K3 ----------------
__global__ void k3_vecmat(const float* __restrict__ W, int mode) {
    int bt = blockIdx.x;
    int col = blockIdx.y * 256 + threadIdx.x;
    __shared__ float v[C_];
    for (int i = threadIdx.x; i < C_; i += 256) v[i] = g_xtime[bt * C_ + i];
    __syncthreads();
    float s = 0.f;
    #pragma unroll 8
    for (int c = 0; c < C_; ++c) s += v[c] * W[(size_t)c * C3 + col];
    float* dst = mode ? g_bias : g_qkvt;
    dst[bt * C3 + col] = s;
}

// ---------------- K4 ----------------
__global__ void k4_temporal() {
    int b = blockIdx.x, h = blockIdx.y, e = threadIdx.x;
    __shared__ float q[T_][DH], k[T_][DH], v[T_][DH];
    __shared__ float kvs[DH][DH + 1], ks[DH], mw[T_];
    for (int t = 0; t < T_; ++t) {
        int base = (b * T_ + t) * C3 + h * DH + e;
        q[t][e] = g_qkvt[base];
        k[t][e] = g_qkvt[base + C_];
        v[t][e] = g_qkvt[base + 2 * C_];
    }
    if (e < T_) mw[e] = 1.f + tanhf(g_mm[b * T_ + e]);
    __syncthreads();
    for (int t = 0; t < T_; ++t) {
        q[t][e] = phi(q[t][e]) * mw[t];
        k[t][e] = phi(k[t][e]);
    }
    __syncthreads();
    {
        float s = 0.f;
        for (int t = 0; t < T_; ++t) s += k[t][e];
        ks[e] = s;
    }
    for (int d = 0; d < DH; ++d) {
        float s = 0.f;
        for (int t = 0; t < T_; ++t) s += k[t][d] * v[t][e];
        kvs[d][e] = s;
    }
    __syncthreads();
    for (int t = 0; t < T_; ++t) {
        float den = 0.f, o = 0.f;
        #pragma unroll
        for (int d = 0; d < DH; ++d) {
            float qd = q[t][d];
            den += qd * ks[d];
            o   += qd * kvs[d][e];
        }
        float z = 1.f / (den + EPS);
        g_tout[(b * T_ + t) * C_ + h * DH + e] = o * z;
    }
}

// ---------------- K5 ----------------
__global__ void k5_prep(const float* __restrict__ temb) {
    int bt = blockIdx.x, c = threadIdx.x;
    g_xtime[bt * C_ + c] = temb[c] + g_tout[bt * C_ + c];
}

// ---------------- KA ----------------
__global__ void kA_split(const float* __restrict__ x) {
    size_t idx = (size_t)blockIdx.x * 256 + threadIdx.x;
    size_t row = idx >> 7;
    int q = (int)(idx & 127);
    float4 v = *(const float4*)(x + (row << 9) + q * 4);
    float f[4] = {v.x, v.y, v.z, v.w};
    uint32_t ph[2], pl[2];
    #pragma unroll
    for (int p = 0; p < 2; ++p) {
        __nv_bfloat16 h0 = __float2bfloat16_rn(f[2 * p]);
        __nv_bfloat16 h1 = __float2bfloat16_rn(f[2 * p + 1]);
        __nv_bfloat16 l0 = __float2bfloat16_rn(f[2 * p] - __bfloat162float(h0));
        __nv_bfloat16 l1 = __float2bfloat16_rn(f[2 * p + 1] - __bfloat162float(h1));
        ph[p] = (uint32_t)__bfloat16_as_ushort(h0) | ((uint32_t)__bfloat16_as_ushort(h1) << 16);
        pl[p] = (uint32_t)__bfloat16_as_ushort(l0) | ((uint32_t)__bfloat16_as_ushort(l1) << 16);
    }
    uint2 hv = {ph[0], ph[1]}, lv = {pl[0], pl[1]};

    int bm2 = (int)(row >> 8);
    int lr  = (int)(row & 255);
    int ch  = q >> 4;
    uint32_t off = (uint32_t)lr * 128 + (uint32_t)(q & 15) * 8;
    uint32_t so = off ^ ((off >> 3) & 0x70);
    char* hiDst = (char*)g_At + ((size_t)(bm2 * 16 + ch)) * AT_B + so;
    *(uint2*)hiDst = hv;
    *(uint2*)(hiDst + 8 * AT_B) = lv;
}

// ---------------- KB ----------------
__global__ void kB_build(const float* __restrict__ W) {
    int n = blockIdx.x * 256 + threadIdx.x;
    int k = blockIdx.y;
    float w = W[(size_t)k * C3 + n];
    __nv_bfloat16 hi = __float2bfloat16_rn(w);
    __nv_bfloat16 lo = __float2bfloat16_rn(w - __bfloat162float(hi));
    int bn = n >> 8, rt = n & 255, ch = k >> 6, col = k & 63;
    uint32_t off = (uint32_t)rt * 128 + (uint32_t)col * 2;
    uint32_t so = off ^ ((off >> 3) & 0x70);
    char* dst = (char*)g_Bt + ((size_t)(bn * 16 + ch)) * BT_B + so;
    *(__nv_bfloat16*)dst = hi;
    *(__nv_bfloat16*)(dst + 8 * BT_B) = lo;
}

// ---------------- K6: 3-stage bulk-async tcgen05 bf16 GEMM, 256x256 tile ----------------
#define SM_TPTR 196608
#define SM_FULL 196616
#define SM_DONE 196640
#define SM_SZ   196664

__global__ void __launch_bounds__(256, 1) k6_mma() {
#if HAS_TCGEN05
    extern __shared__ char smem[];
    uint32_t sb = smem_u32(smem);
    int tid = threadIdx.x;
    int bn = blockIdx.x, bm2 = blockIdx.y;
    int rowBase = bm2 * TM, colBase = bn * TN;

    if (tid < 32) TC_ALLOC(sb + SM_TPTR, 512);
    if (tid == 0) {
        #pragma unroll
        for (int s = 0; s < STAGES; ++s) {
            mbar_init(sb + SM_FULL + 8 * s, 1);
            mbar_init(sb + SM_DONE + 8 * s, 1);
        }
    }
    __syncthreads();
    uint32_t tmem;
    asm volatile("ld.shared.b32 %0, [%1];" : "=r"(tmem) : "r"(sb + SM_TPTR));

    const uint32_t idesc = (1u << 4) | (1u << 7) | (1u << 10) | (16u << 17) | (8u << 24);

    if (tid == 0) {
        const char* Abase = (const char*)g_At + (size_t)bm2 * 16 * AT_B;
        const char* Bbase = (const char*)g_Bt + (size_t)bn * 16 * BT_B;

        #pragma unroll
        for (int p = 0; p < 2; ++p) {
            uint32_t fullb = sb + SM_FULL + 8 * p;
            mbar_expect_tx(fullb, STG_B);
            bulk_g2s(sb + (uint32_t)p * STG_B,        Abase + (size_t)p * AT_B, AT_B, fullb);
            bulk_g2s(sb + (uint32_t)p * STG_B + AT_B, Bbase + (size_t)p * BT_B, BT_B, fullb);
        }

        for (int c = 0; c < NCHUNK; ++c) {
            int s = c % 3;
            mbar_wait(sb + SM_FULL + 8 * s, (c / 3) & 1);

            uint64_t ad0 = make_desc(sb + (uint32_t)s * STG_B);
            uint64_t ad1 = ad0 + 1024;
            uint64_t bd0 = make_desc(sb + (uint32_t)s * STG_B + AT_B);
            uint64_t bd1 = bd0 + 1024;
            #pragma unroll
            for (int ks = 0; ks < 4; ++ks) {
                uint32_t en = (c > 0 || ks > 0) ? 1u : 0u;
                mma_bf16_ss(tmem,       ad0 + 2 * ks, bd0 + 2 * ks, idesc, en);
                mma_bf16_ss(tmem + 128, ad0 + 2 * ks, bd1 + 2 * ks, idesc, en);
                mma_bf16_ss(tmem + 256, ad1 + 2 * ks, bd0 + 2 * ks, idesc, en);
                mma_bf16_ss(tmem + 384, ad1 + 2 * ks, bd1 + 2 * ks, idesc, en);
            }
            tc_commit(sb + SM_DONE + 8 * s);

            int pf = c + 2;
            if (pf < NCHUNK) {
                int sp = pf % 3;
                if (pf >= 3) mbar_wait(sb + SM_DONE + 8 * sp, ((pf - 3) / 3) & 1);
                int at = pf & 15;
                int btile = (pf < 8) ? pf : (pf - 8);
                uint32_t fullb = sb + SM_FULL + 8 * sp;
                mbar_expect_tx(fullb, STG_B);
                bulk_g2s(sb + (uint32_t)sp * STG_B,        Abase + (size_t)at * AT_B, AT_B, fullb);
                bulk_g2s(sb + (uint32_t)sp * STG_B + AT_B, Bbase + (size_t)btile * BT_B, BT_B, fullb);
            }
        }
        mbar_wait(sb + SM_DONE + 8 * 2, 1);
    }
    __syncthreads();
    TC_FENCE_AFTER();

    int lane = tid & 31, w = tid >> 5;
    int wi = w & 3, mh = w >> 2;
    size_t orow = (size_t)(rowBase + mh * 128 + wi * 32 + lane) * C3 + colBase;
    #pragma unroll
    for (int nb = 0; nb < 2; ++nb) {
        for (int b = 0; b < 4; ++b) {
            uint32_t r[32];
            LDTM_X32(r, tmem + mh * 256 + nb * 128 + b * 32);
            TC_WAIT_LD();
            int cb = nb * 128 + b * 32;
            #pragma unroll
            for (int j = 0; j < 32; j += 4) {
                float4 o;
                o.x = __uint_as_float(r[j + 0]);
                o.y = __uint_as_float(r[j + 1]);
                o.z = __uint_as_float(r[j + 2]);
                o.w = __uint_as_float(r[j + 3]);
                *(float4*)(g_qkv + orow + cb + j) = o;
            }
        }
    }
    TC_FENCE_BEFORE();
    __syncthreads();
    if (tid == 0) {
        #pragma unroll
        for (int s = 0; s < STAGES; ++s) {
            mbar_inval(sb + SM_FULL + 8 * s);
            mbar_inval(sb + SM_DONE + 8 * s);
        }
    }
    __syncthreads();
    if (tid < 32) TC_DEALLOC(tmem, 512);
#else
    int tid = threadIdx.x;
    int bn = blockIdx.x, bm2 = blockIdx.y;
    int rowBase = bm2 * TM, colBase = bn * TN;
    for (int e = tid; e < TM * TN; e += 256) {
        int i = e / TN, j = e % TN;
        float s = 0.f;
        for (int kk = 0; kk < NCHUNK * TK; ++kk) {
            int c = kk >> 6, col = kk & 63;
            int at = c & 15;
            int btile = (c < 8) ? c : (c - 8);
            uint32_t ao = (uint32_t)i * 128 + col * 2; ao ^= ((ao >> 3) & 0x70);
            uint32_t bo = (uint32_t)j * 128 + col * 2; bo ^= ((bo >> 3) & 0x70);
            float a = __bfloat162float(*(const __nv_bfloat16*)((const char*)g_At + ((size_t)(bm2 * 16 + at)) * AT_B + ao));
            float b = __bfloat162float(*(const __nv_bfloat16*)((const char*)g_Bt + ((size_t)(bn * 16 + btile)) * BT_B + bo));
            s += a * b;
        }
        g_qkv[(size_t)(rowBase + i) * C3 + colBase + j] = s;
    }
#endif
}

// ---------------- K7: partial kv over 4 token-splits ----------------
__global__ __launch_bounds__(256) void k7_kv() {
    int bt = blockIdx.x, h = blockIdx.y, part = blockIdx.z;
    int t = threadIdx.x;
    int d = t >> 2;
    int esub = t & 3;
    __shared__ __align__(16) float ks[32][DH], vs[32][DH];
    uint64_t acc2[8];
    #pragma unroll
    for (int j = 0; j < 8; ++j) acc2[j] = pack2(0.f, 0.f);
    float accS = 0.f;

    const float* base = g_qkv + (size_t)(bt * NTOK) * C3 + h * DH;
    int lrow = t >> 3;
    int lc = (t & 7) * 8;
    float4 bk0 = *(const float4*)(g_bias + bt * C3 + C_ + h * DH + lc);
    float4 bk1 = *(const float4*)(g_bias + bt * C3 + C_ + h * DH + lc + 4);
    float4 bv0 = *(const float4*)(g_bias + bt * C3 + 2 * C_ + h * DH + lc);
    float4 bv1 = *(const float4*)(g_bias + bt * C3 + 2 * C_ + h * DH + lc + 4);

    int nend = part * TOKP + TOKP;
    for (int n0 = part * TOKP; n0 < nend; n0 += 32) {
        const float* rp = base + (size_t)(n0 + lrow) * C3;
        float4 k0 = *(const float4*)(rp + C_ + lc);
        float4 k1 = *(const float4*)(rp + C_ + lc + 4);
        float4 v0 = *(const float4*)(rp + 2 * C_ + lc);
        float4 v1 = *(const float4*)(rp + 2 * C_ + lc + 4);
        ks[lrow][lc + 0] = phi(k0.x + bk0.x);
        ks[lrow][lc + 1] = phi(k0.y + bk0.y);
        ks[lrow][lc + 2] = phi(k0.z + bk0.z);
        ks[lrow][lc + 3] = phi(k0.w + bk0.w);
        ks[lrow][lc + 4] = phi(k1.x + bk1.x);
        ks[lrow][lc + 5] = phi(k1.y + bk1.y);
        ks[lrow][lc + 6] = phi(k1.z + bk1.z);
        ks[lrow][lc + 7] = phi(k1.w + bk1.w);
        float4 w0 = {v0.x + bv0.x, v0.y + bv0.y, v0.z + bv0.z, v0.w + bv0.w};
        float4 w1 = {v1.x + bv1.x, v1.y + bv1.y, v1.z + bv1.z, v1.w + bv1.w};
        *(float4*)(&vs[lrow][lc])     = w0;
        *(float4*)(&vs[lrow][lc + 4]) = w1;
        __syncthreads();
        #pragma unroll
        for (int r = 0; r < 32; ++r) {
            float pk = ks[r][d];
            uint64_t pk2 = pack2(pk, pk);
            float4 a0 = *(const float4*)(&vs[r][esub * 16]);
            float4 a1 = *(const float4*)(&vs[r][esub * 16 + 4]);
            float4 a2 = *(const float4*)(&vs[r][esub * 16 + 8]);
            float4 a3 = *(const float4*)(&vs[r][esub * 16 + 12]);
            fma2(acc2[0], pk2, pack2(a0.x, a0.y));
            fma2(acc2[1], pk2, pack2(a0.z, a0.w));
            fma2(acc2[2], pk2, pack2(a1.x, a1.y));
            fma2(acc2[3], pk2, pack2(a1.z, a1.w));
            fma2(acc2[4], pk2, pack2(a2.x, a2.y));
            fma2(acc2[5], pk2, pack2(a2.z, a2.w));
            fma2(acc2[6], pk2, pack2(a3.x, a3.y));
            fma2(acc2[7], pk2, pack2(a3.z, a3.w));
            accS += pk;
        }
        __syncthreads();
    }
    float* kvout = g_kvp + (((size_t)(bt * NH + h) * KPART + part) * DH + d) * DH + esub * 16;
    #pragma unroll
    for (int j = 0; j < 4; ++j) {
        float2 p0 = unpack2(acc2[2 * j]);
        float2 p1 = unpack2(acc2[2 * j + 1]);
        float4 o = {p0.x, p0.y, p1.x, p1.y};
        *(float4*)(kvout + 4 * j) = o;
    }
    if (esub == 0) g_ksump[((bt * NH + h) * KPART + part) * DH + d] = accS;
}

// ---------------- K7r: reduce partials ----------------
__global__ __launch_bounds__(256) void k7r_reduce() {
    int bh = blockIdx.x;                  // 0..255 = bt*NH+h
    int t = threadIdx.x;
    const float* src = g_kvp + (size_t)bh * KPART * DH * DH;
    float* dst = g_kv + (size_t)bh * DH * DH;
    for (int i = t * 4; i < DH * DH; i += 256 * 4) {
        float4 s0 = *(const float4*)(src + i);
        float4 s1 = *(const float4*)(src + DH * DH + i);
        float4 s2 = *(const float4*)(src + 2 * DH * DH + i);
        float4 s3 = *(const float4*)(src + 3 * DH * DH + i);
        float4 o = {s0.x + s1.x + s2.x + s3.x, s0.y + s1.y + s2.y + s3.y,
                    s0.z + s1.z + s2.z + s3.z, s0.w + s1.w + s2.w + s3.w};
        *(float4*)(dst + i) = o;
    }
    if (t < DH) {
        const float* sp = g_ksump + bh * KPART * DH;
        g_ksum[bh * DH + t] = sp[t] + sp[DH + t] + sp[2 * DH + t] + sp[3 * DH + t];
    }
}

// ---------------- K8: kv packed in smem, low regs ----------------
__global__ __launch_bounds__(256) void k8_apply(const float* __restrict__ motion,
                                                float* __restrict__ out) {
    int bt = blockIdx.x, h = blockIdx.y, chunk = blockIdx.z;
    int t = threadIdx.x;
    int sub = t >> 6, e = t & 63;
    int lane = t & 31, half = (t >> 5) & 1;
    __shared__ __align__(16) uint64_t kv2s[DH / 2][DH];   // 16 KB: pairs (d=2dp,2dp+1) at column e
    __shared__ __align__(8) float qs[4][DH];
    __shared__ float dpar[4][2];

    const float* kvg = g_kv + (size_t)(bt * NH + h) * DH * DH;
    for (int i = t; i < (DH / 2) * DH; i += 256) {
        int dp = i >> 6, e2 = i & 63;
        kv2s[dp][e2] = pack2(kvg[(2 * dp) * DH + e2], kvg[(2 * dp + 1) * DH + e2]);
    }
    float kse = g_ksum[(bt * NH + h) * DH + e];
    float bq = g_bias[bt * C3 + h * DH + e];
    __syncthreads();

    int n0 = chunk * 96;
    for (int g = 0; g < 96; g += 4) {
        int n = n0 + g + sub;
        float raw = g_qkv[(size_t)(bt * NTOK + n) * C3 + h * DH + e] + bq;
        float mm = motion[bt * NTOK + n];
        float th;
        asm("tanh.approx.f32 %0, %1;" : "=f"(th) : "f"(mm));
        float qv = phi(raw) * (1.f + th);
        qs[sub][e] = qv;
        float dp = qv * kse;
        #pragma unroll
        for (int off = 16; off > 0; off >>= 1)
            dp += __shfl_xor_sync(0xffffffffu, dp, off);
        if (lane == 0) dpar[sub][half] = dp;
        __syncthreads();
        float den = dpar[sub][0] + dpar[sub][1];
        uint64_t o2 = pack2(0.f, 0.f);
        #pragma unroll
        for (int dpp = 0; dpp < DH / 2; ++dpp) {
            uint64_t q2 = *(const uint64_t*)(&qs[sub][2 * dpp]);   // broadcast LDS.64
            fma2(o2, q2, kv2s[dpp][e]);
        }
        float2 of = unpack2(o2);
        float o = of.x + of.y;
        out[(size_t)(bt * NTOK + n) * C_ + h * DH + e] = o / (den + EPS);
        __syncthreads();
    }
}

// ---------------- launch ----------------
extern "C" void kernel_launch(void* const* d_in, const int* in_sizes, int n_in,
                              void* d_out, int out_size) {
    const float* x      = (const float*)d_in[0];
    const float* motion = (const float*)d_in[1];
    const float* W      = (const float*)d_in[2];
    const float* temb   = (const float*)d_in[3];
    float* out = (float*)d_out;

    cudaFuncSetAttribute(k6_mma, cudaFuncAttributeMaxDynamicSharedMemorySize, SM_SZ);

    kA_split<<<(int)(((size_t)M_ * 128) / 256), 256>>>(x);
    kB_build<<<dim3(C3 / 256, C_), 256>>>(W);
    k1_partial<<<dim3(BT, 8), 512>>>(x, motion);
    k6_mma<<<dim3(NBN, NBM2), 256, SM_SZ>>>();      // profile slot idx 3
    k2_final<<<BT, 512>>>(temb);
    k3_vecmat<<<dim3(BT, 6), 256>>>(W, 0);
    k4_temporal<<<dim3(B_, NH), 64>>>();
    k5_prep<<<BT, 512>>>(temb);
    k3_vecmat<<<dim3(BT, 6), 256>>>(W, 1);
    k7_kv<<<dim3(BT, NH, KPART), 256>>>();
    k7r_reduce<<<BT * NH, 256>>>();
    k8_apply<<<dim3(BT, NH, NTOK / 96), 256>>>(motion, out);
}

// round 14
// speedup vs baseline: 1.6017x; 1.5428x over previous
#include <cuda_runtime.h>
#include <cuda_bf16.h>
#include <math.h>
#include <stdint.h>

#define B_   2
#define T_   16
#define BT   32
#define NTOK 2304
#define C_   512
#define C3   1536
#define NH   8
#define DH   64
#define EPS  1e-6f

#define M_   (BT * NTOK)   // 73728
#define TM   256
#define TN   256
#define TK   64
#define NCHUNK 24
#define NBM2  (M_ / TM)    // 288
#define NBN   (C3 / TN)    // 6
#define AT_B  32768
#define BT_B  32768
#define STAGES 3
#define STG_B  (AT_B + BT_B)
#define NTILE 9            // 2304/256 token tiles per frame

#if defined(__CUDA_ARCH_FEAT_SM103_ALL) || defined(__CUDA_ARCH_FEAT_SM100_ALL) || \
    (defined(__CUDA_ARCH_SPECIFIC__) && (__CUDA_ARCH_SPECIFIC__ == 1030))
#define HAS_TCGEN05 1
#else
#define HAS_TCGEN05 0
#endif

// ---------------- scratch ----------------
__device__ float g_qkv[(size_t)BT * NTOK * C3];   // only q section (cols<512) used now
__device__ __nv_bfloat16 g_At[(size_t)NBM2 * 16 * (AT_B / 2)];
__device__ __nv_bfloat16 g_Bt[(size_t)NBN * 16 * (BT_B / 2)];
__device__ float g_part[BT * 8 * C_];
__device__ float g_partmm[BT * 8];
__device__ float g_xtime[BT * C_];
__device__ float g_mm[BT];
__device__ float g_qkvt[BT * C3];
__device__ float g_tout[BT * C_];
__device__ float g_bias[BT * C3];
__device__ float g_kv[BT * NH * DH * DH];
__device__ float g_ksum[BT * NH * DH];
__device__ float g_kvp[(size_t)BT * NH * NTILE * DH * DH];
__device__ float g_ksump[BT * NH * NTILE * DH];

__device__ __forceinline__ float phi(float x) {
    return x > 0.f ? x + 1.f : expf(x);
}

// ---------------- f32x2 helpers ----------------
__device__ __forceinline__ uint64_t pack2(float lo, float hi) {
    uint64_t r; asm("mov.b64 %0, {%1, %2};" : "=l"(r) : "f"(lo), "f"(hi)); return r;
}
__device__ __forceinline__ float2 unpack2(uint64_t v) {
    float2 f; asm("mov.b64 {%0, %1}, %2;" : "=f"(f.x), "=f"(f.y) : "l"(v)); return f;
}
__device__ __forceinline__ void fma2(uint64_t& d, uint64_t a, uint64_t b) {
#if HAS_TCGEN05
    asm("fma.rn.f32x2 %0, %1, %2, %3;" : "=l"(d) : "l"(a), "l"(b), "l"(d));
#else
    float2 fd = unpack2(d), fa = unpack2(a), fb = unpack2(b);
    fd.x = fmaf(fa.x, fb.x, fd.x);
    fd.y = fmaf(fa.y, fb.y, fd.y);
    d = pack2(fd.x, fd.y);
#endif
}

// ---------------- ptx helpers ----------------
__device__ __forceinline__ uint32_t smem_u32(const void* p) {
    uint32_t a;
    asm("{ .reg .u64 t; cvta.to.shared.u64 t, %1; cvt.u32.u64 %0, t; }" : "=r"(a) : "l"(p));
    return a;
}
static __device__ __forceinline__ uint64_t make_desc(uint32_t addr) {
    const uint64_t base = (uint64_t(2) << 61) | (uint64_t(1) << 46) | (uint64_t(64) << 32) | (uint64_t(1) << 16);
    return base | ((uint64_t)(addr >> 4) & 0x3FFF);
}
__device__ __forceinline__ void mbar_init(uint32_t a, uint32_t cnt) {
    asm volatile("mbarrier.init.shared.b64 [%0], %1;" :: "r"(a), "r"(cnt) : "memory");
}
__device__ __forceinline__ void mbar_inval(uint32_t a) {
    asm volatile("mbarrier.inval.shared.b64 [%0];" :: "r"(a) : "memory");
}
__device__ __forceinline__ void mbar_wait(uint32_t a, uint32_t parity) {
    asm volatile(
        "{\n\t.reg .pred P1;\n\tWL_%=:\n\t"
        "mbarrier.try_wait.parity.acquire.cta.shared::cta.b64 P1, [%0], %1, 0x989680;\n\t"
        "@P1 bra.uni WD_%=;\n\tbra.uni WL_%=;\n\tWD_%=:\n\t}"
        :: "r"(a), "r"(parity) : "memory");
}
__device__ __forceinline__ void mbar_expect_tx(uint32_t a, uint32_t bytes) {
    asm volatile("mbarrier.arrive.expect_tx.shared.b64 _, [%0], %1;"
                 :: "r"(a), "r"(bytes) : "memory");
}
__device__ __forceinline__ void bulk_g2s(uint32_t dst, const void* src, uint32_t bytes, uint32_t mbar) {
    asm volatile("cp.async.bulk.shared::cta.global.mbarrier::complete_tx::bytes [%0], [%1], %2, [%3];"
                 :: "r"(dst), "l"(src), "r"(bytes), "r"(mbar) : "memory");
}

#if HAS_TCGEN05
__device__ __forceinline__ void mma_bf16_ss(uint32_t d, uint64_t ad, uint64_t bd, uint32_t idesc, uint32_t en) {
    asm volatile(
        "{\n\t.reg .pred p;\n\tsetp.ne.u32 p, %4, 0;\n\t"
        "tcgen05.mma.cta_group::1.kind::f16 [%0], %1, %2, %3, {%5, %5, %5, %5}, p;\n\t}"
        :: "r"(d), "l"(ad), "l"(bd), "r"(idesc), "r"(en), "r"(0u) : "memory");
}
__device__ __forceinline__ void tc_commit(uint32_t mbar) {
    asm volatile("tcgen05.commit.cta_group::1.mbarrier::arrive::one.shared::cluster.b64 [%0];"
                 :: "r"(mbar) : "memory");
}
#define TC_ALLOC(sa, n)  asm volatile("tcgen05.alloc.cta_group::1.sync.aligned.shared::cta.b32 [%0], %1;" :: "r"(sa), "r"(n) : "memory")
#define TC_DEALLOC(t, n) asm volatile("tcgen05.dealloc.cta_group::1.sync.aligned.b32 %0, %1;" :: "r"(t), "r"(n))
#define TC_FENCE_AFTER()  asm volatile("tcgen05.fence::after_thread_sync;" ::: "memory")
#define TC_FENCE_BEFORE() asm volatile("tcgen05.fence::before_thread_sync;" ::: "memory")
#define TC_WAIT_LD() asm volatile("tcgen05.wait::ld.sync.aligned;" ::: "memory")
#define LDTM_X32(r, a) \
    asm volatile("tcgen05.ld.sync.aligned.32x32b.x32.b32 " \
        "{%0, %1, %2, %3, %4, %5, %6, %7, %8, %9, %10, %11, %12, %13, %14, %15, " \
        "%16, %17, %18, %19, %20, %21, %22, %23, %24, %25, %26, %27, %28, %29, %30, %31}, [%32];" \
        : "=r"((r)[0]), "=r"((r)[1]), "=r"((r)[2]), "=r"((r)[3]), "=r"((r)[4]), "=r"((r)[5]), "=r"((r)[6]), "=r"((r)[7]), \
          "=r"((r)[8]), "=r"((r)[9]), "=r"((r)[10]), "=r"((r)[11]), "=r"((r)[12]), "=r"((r)[13]), "=r"((r)[14]), "=r"((r)[15]), \
          "=r"((r)[16]), "=r"((r)[17]), "=r"((r)[18]), "=r"((r)[19]), "=r"((r)[20]), "=r"((r)[21]), "=r"((r)[22]), "=r"((r)[23]), \
          "=r"((r)[24]), "=r"((r)[25]), "=r"((r)[26]), "=r"((r)[27]), "=r"((r)[28]), "=r"((r)[29]), "=r"((r)[30]), "=r"((r)[31]) \
        : "r"(a))
#endif

// ---------------- K1 ----------------
__global__ void k1_partial(const float* __restrict__ x, const float* __restrict__ motion) {
    int bt = blockIdx.x, chunk = blockIdx.y;
    int c = threadIdx.x;
    const int RPC = NTOK / 8;
    int n0 = chunk * RPC;
    const float* xp = x + ((size_t)(bt * NTOK + n0)) * C_ + c;
    float s = 0.f;
    for (int r = 0; r < RPC; ++r) s += xp[(size_t)r * C_];
    g_part[(bt * 8 + chunk) * C_ + c] = s;

    __shared__ float sm[512];
    float m = 0.f;
    for (int r = c; r < RPC; r += 512) m += motion[bt * NTOK + n0 + r];
    sm[c] = m;
    __syncthreads();
    for (int off = 256; off > 0; off >>= 1) {
        if (c < off) sm[c] += sm[c + off];
        __syncthreads();
    }
    if (c == 0) g_partmm[bt * 8 + chunk] = sm[0];
}

// ---------------- K2 ----------------
__global__ void k2_final(const float* __restrict__ temb) {
    int bt = blockIdx.x, c = threadIdx.x;
    float s = 0.f;
    for (int j = 0; j < 8; ++j) s += g_part[(bt * 8 + j) * C_ + c];
    g_xtime[bt * C_ + c] = s * (1.f / NTOK) + temb[c];
    if (c == 0) {
        float m = 0.f;
        for (int j = 0; j < 8; ++j) m += g_partmm[bt * 8 + j];
        g_mm[bt] = m * (1.f / NTOK);
    }
}

// ---------------- K3 ----------------
__global__ void k3_vecmat(const float* __restrict__ W, int mode) {
    int bt = blockIdx.x;
    int col = blockIdx.y * 256 + threadIdx.x;
    __shared__ float v[C_];
    for (int i = threadIdx.x; i < C_; i += 256) v[i] = g_xtime[bt * C_ + i];
    __syncthreads();
    float s = 0.f;
    #pragma unroll 8
    for (int c = 0; c < C_; ++c) s += v[c] * W[(size_t)c * C3 + col];
    float* dst = mode ? g_bias : g_qkvt;
    dst[bt * C3 + col] = s;
}

// ---------------- K4 ----------------
__global__ void k4_temporal() {
    int b = blockIdx.x, h = blockIdx.y, e = threadIdx.x;
    __shared__ float q[T_][DH], k[T_][DH], v[T_][DH];
    __shared__ float kvs[DH][DH + 1], ks[DH], mw[T_];
    for (int t = 0; t < T_; ++t) {
        int base = (b * T_ + t) * C3 + h * DH + e;
        q[t][e] = g_qkvt[base];
        k[t][e] = g_qkvt[base + C_];
        v[t][e] = g_qkvt[base + 2 * C_];
    }
    if (e < T_) mw[e] = 1.f + tanhf(g_mm[b * T_ + e]);
    __syncthreads();
    for (int t = 0; t < T_; ++t) {
        q[t][e] = phi(q[t][e]) * mw[t];
        k[t][e] = phi(k[t][e]);
    }
    __syncthreads();
    {
        float s = 0.f;
        for (int t = 0; t < T_; ++t) s += k[t][e];
        ks[e] = s;
    }
    for (int d = 0; d < DH; ++d) {
        float s = 0.f;
        for (int t = 0; t < T_; ++t) s += k[t][d] * v[t][e];
        kvs[d][e] = s;
    }
    __syncthreads();
    for (int t = 0; t < T_; ++t) {
        float den = 0.f, o = 0.f;
        #pragma unroll
        for (int d = 0; d < DH; ++d) {
            float qd = q[t][d];
            den += qd * ks[d];
            o   += qd * kvs[d][e];
        }
        float z = 1.f / (den + EPS);
        g_tout[(b * T_ + t) * C_ + h * DH + e] = o * z;
    }
}

// ---------------- K5 ----------------
__global__ void k5_prep(const float* __restrict__ temb) {
    int bt = blockIdx.x, c = threadIdx.x;
    g_xtime[bt * C_ + c] = temb[c] + g_tout[bt * C_ + c];
}

// ---------------- KA ----------------
__global__ void kA_split(const float* __restrict__ x) {
    size_t idx = (size_t)blockIdx.x * 256 + threadIdx.x;
    size_t row = idx >> 7;
    int q = (int)(idx & 127);
    float4 v = *(const float4*)(x + (row << 9) + q * 4);
    float f[4] = {v.x, v.y, v.z, v.w};
    uint32_t ph[2], pl[2];
    #pragma unroll
    for (int p = 0; p < 2; ++p) {
        __nv_bfloat16 h0 = __float2bfloat16_rn(f[2 * p]);
        __nv_bfloat16 h1 = __float2bfloat16_rn(f[2 * p + 1]);
        __nv_bfloat16 l0 = __float2bfloat16_rn(f[2 * p] - __bfloat162float(h0));
        __nv_bfloat16 l1 = __float2bfloat16_rn(f[2 * p + 1] - __bfloat162float(h1));
        ph[p] = (uint32_t)__bfloat16_as_ushort(h0) | ((uint32_t)__bfloat16_as_ushort(h1) << 16);
        pl[p] = (uint32_t)__bfloat16_as_ushort(l0) | ((uint32_t)__bfloat16_as_ushort(l1) << 16);
    }
    uint2 hv = {ph[0], ph[1]}, lv = {pl[0], pl[1]};

    int bm2 = (int)(row >> 8);
    int lr  = (int)(row & 255);
    int ch  = q >> 4;
    uint32_t off = (uint32_t)lr * 128 + (uint32_t)(q & 15) * 8;
    uint32_t so = off ^ ((off >> 3) & 0x70);
    char* hiDst = (char*)g_At + ((size_t)(bm2 * 16 + ch)) * AT_B + so;
    *(uint2*)hiDst = hv;
    *(uint2*)(hiDst + 8 * AT_B) = lv;
}

// ---------------- KB: B tiles with head-paired column layout ----------------
__global__ void kB_build(const float* __restrict__ W) {
    int n = blockIdx.x * 256 + threadIdx.x;
    int k = blockIdx.y;
    float w = W[(size_t)k * C3 + n];
    __nv_bfloat16 hi = __float2bfloat16_rn(w);
    __nv_bfloat16 lo = __float2bfloat16_rn(w - __bfloat162float(hi));
    int np;
    if (n < 512) np = n;
    else if (n < 1024) { int h = (n - 512) >> 6; np = 512 + 128 * h + ((n - 512) & 63); }
    else               { int h = (n - 1024) >> 6; np = 512 + 128 * h + 64 + ((n - 1024) & 63); }
    int bn = np >> 8, rt = np & 255, ch = k >> 6, col = k & 63;
    uint32_t off = (uint32_t)rt * 128 + (uint32_t)col * 2;
    uint32_t so = off ^ ((off >> 3) & 0x70);
    char* dst = (char*)g_Bt + ((size_t)(bn * 16 + ch)) * BT_B + so;
    *(__nv_bfloat16*)dst = hi;
    *(__nv_bfloat16*)(dst + 8 * BT_B) = lo;
}

// ---------------- K6: fused GEMM; kv CTAs compute partial kv in epilogue ----------------
#define SM_TPTR 196608
#define SM_FULL 196616
#define SM_DONE 196640
#define SM_BIAS 196672
#define SM_SZ   197696
#define PSTR    132

__global__ void __launch_bounds__(256, 1) k6_mma() {
#if HAS_TCGEN05
    extern __shared__ char smem[];
    uint32_t sb = smem_u32(smem);
    int tid = threadIdx.x;
    int bn = blockIdx.x, bm2 = blockIdx.y;
    int rowBase = bm2 * TM, colBase = bn * TN;
    int bt = rowBase / NTOK;

    if (bn >= 2) {
        float* bias_s = (float*)(smem + SM_BIAS);
        for (int c = tid; c < TN; c += 256) {
            int hh = c >> 7, local = c & 127;
            int h = (bn - 2) * 2 + hh;
            int orig = (local < 64) ? (C_ + 64 * h + local) : (2 * C_ + 64 * h + (local - 64));
            bias_s[c] = g_bias[bt * C3 + orig];
        }
    }
    __syncthreads();

    if (tid < 32) TC_ALLOC(sb + SM_TPTR, 512);
    if (tid == 0) {
        #pragma unroll
        for (int s = 0; s < STAGES; ++s) {
            mbar_init(sb + SM_FULL + 8 * s, 1);
            mbar_init(sb + SM_DONE + 8 * s, 1);
        }
    }
    __syncthreads();
    uint32_t tmem;
    asm volatile("ld.shared.b32 %0, [%1];" : "=r"(tmem) : "r"(sb + SM_TPTR));

    const uint32_t idesc = (1u << 4) | (1u << 7) | (1u << 10) | (16u << 17) | (8u << 24);

    if (tid == 0) {
        const char* Abase = (const char*)g_At + (size_t)bm2 * 16 * AT_B;
        const char* Bbase = (const char*)g_Bt + (size_t)bn * 16 * BT_B;

        #pragma unroll
        for (int p = 0; p < 2; ++p) {
            uint32_t fullb = sb + SM_FULL + 8 * p;
            mbar_expect_tx(fullb, STG_B);
            bulk_g2s(sb + (uint32_t)p * STG_B,        Abase + (size_t)p * AT_B, AT_B, fullb);
            bulk_g2s(sb + (uint32_t)p * STG_B + AT_B, Bbase + (size_t)p * BT_B, BT_B, fullb);
        }

        for (int c = 0; c < NCHUNK; ++c) {
            int s = c % 3;
            mbar_wait(sb + SM_FULL + 8 * s, (c / 3) & 1);

            uint64_t ad0 = make_desc(sb + (uint32_t)s * STG_B);
            uint64_t ad1 = ad0 + 1024;
            uint64_t bd0 = make_desc(sb + (uint32_t)s * STG_B + AT_B);
            uint64_t bd1 = bd0 + 1024;
            #pragma unroll
            for (int ks = 0; ks < 4; ++ks) {
                uint32_t en = (c > 0 || ks > 0) ? 1u : 0u;
                mma_bf16_ss(tmem,       ad0 + 2 * ks, bd0 + 2 * ks, idesc, en);
                mma_bf16_ss(tmem + 128, ad0 + 2 * ks, bd1 + 2 * ks, idesc, en);
                mma_bf16_ss(tmem + 256, ad1 + 2 * ks, bd0 + 2 * ks, idesc, en);
                mma_bf16_ss(tmem + 384, ad1 + 2 * ks, bd1 + 2 * ks, idesc, en);
            }
            tc_commit(sb + SM_DONE + 8 * s);

            int pf = c + 2;
            if (pf < NCHUNK) {
                int sp = pf % 3;
                if (pf >= 3) mbar_wait(sb + SM_DONE + 8 * sp, ((pf - 3) / 3) & 1);
                int at = pf & 15;
                int btile = (pf < 8) ? pf : (pf - 8);
                uint32_t fullb = sb + SM_FULL + 8 * sp;
                mbar_expect_tx(fullb, STG_B);
                bulk_g2s(sb + (uint32_t)sp * STG_B,        Abase + (size_t)at * AT_B, AT_B, fullb);
                bulk_g2s(sb + (uint32_t)sp * STG_B + AT_B, Bbase + (size_t)btile * BT_B, BT_B, fullb);
            }
        }
        mbar_wait(sb + SM_DONE + 8 * 2, 1);
    }
    __syncthreads();
    TC_FENCE_AFTER();

    int lane = tid & 31, w = tid >> 5;
    int wi = w & 3, mh = w >> 2;

    if (bn < 2) {
        size_t orow = (size_t)(rowBase + mh * 128 + wi * 32 + lane) * C3 + colBase;
        #pragma unroll
        for (int nb = 0; nb < 2; ++nb) {
            for (int b = 0; b < 4; ++b) {
                uint32_t r[32];
                LDTM_X32(r, tmem + mh * 256 + nb * 128 + b * 32);
                TC_WAIT_LD();
                int cb = nb * 128 + b * 32;
                #pragma unroll
                for (int j = 0; j < 32; j += 4) {
                    float4 o;
                    o.x = __uint_as_float(r[j + 0]);
                    o.y = __uint_as_float(r[j + 1]);
                    o.z = __uint_as_float(r[j + 2]);
                    o.w = __uint_as_float(r[j + 3]);
                    *(float4*)(g_qkv + orow + cb + j) = o;
                }
            }
        }
    } else {
        float* ps = (float*)smem;
        const float* bias_s = (const float*)(smem + SM_BIAS);
        int tile = (rowBase - bt * NTOK) >> 8;
        int tok = mh * 128 + wi * 32 + lane;

        #pragma unroll
        for (int hh = 0; hh < 2; ++hh) {
            #pragma unroll
            for (int b = 0; b < 4; ++b) {
                uint32_t r[32];
                LDTM_X32(r, tmem + mh * 256 + hh * 128 + b * 32);
                TC_WAIT_LD();
                #pragma unroll
                for (int j = 0; j < 32; j += 4) {
                    int cl = b * 32 + j;
                    float4 o;
                    o.x = __uint_as_float(r[j + 0]) + bias_s[hh * 128 + cl + 0];
                    o.y = __uint_as_float(r[j + 1]) + bias_s[hh * 128 + cl + 1];
                    o.z = __uint_as_float(r[j + 2]) + bias_s[hh * 128 + cl + 2];
                    o.w = __uint_as_float(r[j + 3]) + bias_s[hh * 128 + cl + 3];
                    if (cl < 64) { o.x = phi(o.x); o.y = phi(o.y); o.z = phi(o.z); o.w = phi(o.w); }
                    *(float4*)(&ps[tok * PSTR + cl]) = o;
                }
            }
            __syncthreads();

            int d4 = tid >> 4, e4 = tid & 15;
            uint64_t acc2[8];
            #pragma unroll
            for (int i = 0; i < 8; ++i) acc2[i] = pack2(0.f, 0.f);
            for (int n = 0; n < 256; ++n) {
                const float* row = &ps[n * PSTR];
                float4 kd = *(const float4*)(&row[d4 * 4]);
                uint64_t v0 = *(const uint64_t*)(&row[64 + e4 * 4]);
                uint64_t v1 = *(const uint64_t*)(&row[64 + e4 * 4 + 2]);
                uint64_t kx = pack2(kd.x, kd.x), ky = pack2(kd.y, kd.y);
                uint64_t kz = pack2(kd.z, kd.z), kw = pack2(kd.w, kd.w);
                fma2(acc2[0], kx, v0); fma2(acc2[1], kx, v1);
                fma2(acc2[2], ky, v0); fma2(acc2[3], ky, v1);
                fma2(acc2[4], kz, v0); fma2(acc2[5], kz, v1);
                fma2(acc2[6], kw, v0); fma2(acc2[7], kw, v1);
            }
            int h = (bn - 2) * 2 + hh;
            float* dst = g_kvp + ((size_t)((bt * NH + h) * NTILE + tile)) * (DH * DH);
            #pragma unroll
            for (int i = 0; i < 4; ++i) {
                float2 p0 = unpack2(acc2[i * 2]);
                float2 p1 = unpack2(acc2[i * 2 + 1]);
                float4 o = {p0.x, p0.y, p1.x, p1.y};
                *(float4*)(&dst[(d4 * 4 + i) * DH + e4 * 4]) = o;
            }
            if (tid < 64) {
                float s = 0.f;
                for (int n = 0; n < 256; ++n) s += ps[n * PSTR + tid];
                g_ksump[((bt * NH + h) * NTILE + tile) * DH + tid] = s;
            }
            __syncthreads();
        }
    }

    TC_FENCE_BEFORE();
    __syncthreads();
    if (tid == 0) {
        #pragma unroll
        for (int s = 0; s < STAGES; ++s) {
            mbar_inval(sb + SM_FULL + 8 * s);
            mbar_inval(sb + SM_DONE + 8 * s);
        }
    }
    __syncthreads();
    if (tid < 32) TC_DEALLOC(tmem, 512);
#else
    // Fallback for the compute_103 PTX pass (never executed on GB300).
    int tid = threadIdx.x;
    int bn = blockIdx.x, bm2 = blockIdx.y;
    int rowBase = bm2 * TM, colBase = bn * TN;
    int bt = rowBase / NTOK;
    auto gemm_elem = [&](int i, int j) {
        float s = 0.f;
        for (int kk = 0; kk < NCHUNK * TK; ++kk) {
            int c = kk >> 6, col = kk & 63;
            int at = c & 15;
            int btile = (c < 8) ? c : (c - 8);
            uint32_t ao = (uint32_t)i * 128 + col * 2; ao ^= ((ao >> 3) & 0x70);
            uint32_t bo = (uint32_t)j * 128 + col * 2; bo ^= ((bo >> 3) & 0x70);
            float a = __bfloat162float(*(const __nv_bfloat16*)((const char*)g_At + ((size_t)(bm2 * 16 + at)) * AT_B + ao));
            float b = __bfloat162float(*(const __nv_bfloat16*)((const char*)g_Bt + ((size_t)(bn * 16 + btile)) * BT_B + bo));
            s += a * b;
        }
        return s;
    };
    if (bn < 2) {
        for (int e = tid; e < TM * TN; e += 256) {
            int i = e / TN, j = e % TN;
            g_qkv[(size_t)(rowBase + i) * C3 + colBase + j] = gemm_elem(i, j);
        }
    } else {
        int tile = (rowBase - bt * NTOK) >> 8;
        for (int hh = 0; hh < 2; ++hh) {
            int h = (bn - 2) * 2 + hh;
            for (int de = tid; de < DH * DH; de += 256) {
                int d = de / DH, ee = de % DH;
                float acc = 0.f, ss = 0.f;
                for (int i = 0; i < TM; ++i) {
                    float kb = g_bias[bt * C3 + C_ + 64 * h + d];
                    float vb = g_bias[bt * C3 + 2 * C_ + 64 * h + ee];
                    float pk = phi(gemm_elem(i, hh * 128 + d) + kb);
                    float vv = gemm_elem(i, hh * 128 + 64 + ee) + vb;
                    acc += pk * vv;
                    if (ee == 0) ss += pk;
                }
                g_kvp[((size_t)((bt * NH + h) * NTILE + tile)) * (DH * DH) + d * DH + ee] = acc;
                if (ee == 0) g_ksump[((bt * NH + h) * NTILE + tile) * DH + d] = ss;
            }
        }
    }
#endif
}

// ---------------- K7r: reduce 9 tile-partials ----------------
__global__ __launch_bounds__(256) void k7r_reduce() {
    int bh = blockIdx.x;
    int t = threadIdx.x;
    const float* src = g_kvp + (size_t)bh * NTILE * DH * DH;
    float* dst = g_kv + (size_t)bh * DH * DH;
    for (int i = t * 4; i < DH * DH; i += 256 * 4) {
        float4 a = {0.f, 0.f, 0.f, 0.f};
        #pragma unroll
        for (int p = 0; p < NTILE; ++p) {
            float4 s = *(const float4*)(src + (size_t)p * DH * DH + i);
            a.x += s.x; a.y += s.y; a.z += s.z; a.w += s.w;
        }
        *(float4*)(dst + i) = a;
    }
    if (t < DH) {
        const float* sp = g_ksump + bh * NTILE * DH;
        float s = 0.f;
        #pragma unroll
        for (int p = 0; p < NTILE; ++p) s += sp[p * DH + t];
        g_ksum[bh * DH + t] = s;
    }
}

// ---------------- K8 ----------------
__global__ __launch_bounds__(256) void k8_apply(const float* __restrict__ motion,
                                                float* __restrict__ out) {
    int bt = blockIdx.x, h = blockIdx.y, chunk = blockIdx.z;
    int t = threadIdx.x;
    int sub = t >> 6, e = t & 63;
    int lane = t & 31, half = (t >> 5) & 1;
    __shared__ __align__(16) uint64_t kv2s[DH / 2][DH];
    __shared__ __align__(8) float qs[4][DH];
    __shared__ float dpar[4][2];

    const float* kvg = g_kv + (size_t)(bt * NH + h) * DH * DH;
    for (int i = t; i < (DH / 2) * DH; i += 256) {
        int dp = i >> 6, e2 = i & 63;
        kv2s[dp][e2] = pack2(kvg[(2 * dp) * DH + e2], kvg[(2 * dp + 1) * DH + e2]);
    }
    float kse = g_ksum[(bt * NH + h) * DH + e];
    float bq = g_bias[bt * C3 + h * DH + e];
    __syncthreads();

    int n0 = chunk * 96;
    for (int g = 0; g < 96; g += 4) {
        int n = n0 + g + sub;
        float raw = g_qkv[(size_t)(bt * NTOK + n) * C3 + h * DH + e] + bq;
        float mm = motion[bt * NTOK + n];
        float th;
        asm("tanh.approx.f32 %0, %1;" : "=f"(th) : "f"(mm));
        float qv = phi(raw) * (1.f + th);
        qs[sub][e] = qv;
        float dp = qv * kse;
        #pragma unroll
        for (int off = 16; off > 0; off >>= 1)
            dp += __shfl_xor_sync(0xffffffffu, dp, off);
        if (lane == 0) dpar[sub][half] = dp;
        __syncthreads();
        float den = dpar[sub][0] + dpar[sub][1];
        uint64_t o2 = pack2(0.f, 0.f);
        #pragma unroll
        for (int dpp = 0; dpp < DH / 2; ++dpp) {
            uint64_t q2 = *(const uint64_t*)(&qs[sub][2 * dpp]);
            fma2(o2, q2, kv2s[dpp][e]);
        }
        float2 of = unpack2(o2);
        float o = of.x + of.y;
        out[(size_t)(bt * NTOK + n) * C_ + h * DH + e] = o / (den + EPS);
        __syncthreads();
    }
}

// ---------------- launch ----------------
extern "C" void kernel_launch(void* const* d_in, const int* in_sizes, int n_in,
                              void* d_out, int out_size) {
    const float* x      = (const float*)d_in[0];
    const float* motion = (const float*)d_in[1];
    const float* W      = (const float*)d_in[2];
    const float* temb   = (const float*)d_in[3];
    float* out = (float*)d_out;

    cudaFuncSetAttribute(k6_mma, cudaFuncAttributeMaxDynamicSharedMemorySize, SM_SZ);

    kA_split<<<(int)(((size_t)M_ * 128) / 256), 256>>>(x);
    kB_build<<<dim3(C3 / 256, C_), 256>>>(W);
    k1_partial<<<dim3(BT, 8), 512>>>(x, motion);
    k2_final<<<BT, 512>>>(temb);
    k3_vecmat<<<dim3(BT, 6), 256>>>(W, 0);
    k4_temporal<<<dim3(B_, NH), 64>>>();
    k5_prep<<<BT, 512>>>(temb);
    k3_vecmat<<<dim3(BT, 6), 256>>>(W, 1);
    k6_mma<<<dim3(NBN, NBM2), 256, SM_SZ>>>();
    k7r_reduce<<<BT * NH, 256>>>();
    k8_apply<<<dim3(BT, NH, NTOK / 96), 256>>>(motion, out);
}

// round 16
// speedup vs baseline: 1.9841x; 1.2388x over previous
#include <cuda_runtime.h>
#include <cuda_bf16.h>
#include <math.h>
#include <stdint.h>

#define B_   2
#define T_   16
#define BT   32
#define NTOK 2304
#define C_   512
#define C3   1536
#define NH   8
#define DH   64
#define EPS  1e-6f

#define M_   (BT * NTOK)   // 73728
#define TM   256
#define TN   256
#define TK   64
#define NCHUNK 24
#define NBM2  (M_ / TM)    // 288
#define NBN   (C3 / TN)    // 6
#define AT_B  32768
#define BT_B  32768
#define STAGES 3
#define STG_B  (AT_B + BT_B)
#define NTILE 9

#if defined(__CUDA_ARCH_FEAT_SM103_ALL) || defined(__CUDA_ARCH_FEAT_SM100_ALL) || \
    (defined(__CUDA_ARCH_SPECIFIC__) && (__CUDA_ARCH_SPECIFIC__ == 1030))
#define HAS_TCGEN05 1
#else
#define HAS_TCGEN05 0
#endif

// ---------------- scratch ----------------
__device__ __nv_bfloat16 g_At[(size_t)NBM2 * 16 * (AT_B / 2)];
__device__ __nv_bfloat16 g_Bt[(size_t)NBN * 16 * (BT_B / 2)];
__device__ float g_part[BT * 8 * C_];
__device__ float g_partmm[BT * 8];
__device__ float g_xtime[BT * C_];
__device__ float g_mm[BT];
__device__ float g_qkvt[BT * C3];
__device__ float g_tout[BT * C_];
__device__ float g_bias[BT * C3];
__device__ float g_kv[BT * NH * DH * DH];
__device__ float g_ksum[BT * NH * DH];
__device__ float g_kvp[(size_t)BT * NH * NTILE * DH * DH];
__device__ float g_ksump[BT * NH * NTILE * DH];

__device__ __forceinline__ float phi(float x) {
    return x > 0.f ? x + 1.f : expf(x);
}

// ---------------- f32x2 helpers ----------------
__device__ __forceinline__ uint64_t pack2(float lo, float hi) {
    uint64_t r; asm("mov.b64 %0, {%1, %2};" : "=l"(r) : "f"(lo), "f"(hi)); return r;
}
__device__ __forceinline__ float2 unpack2(uint64_t v) {
    float2 f; asm("mov.b64 {%0, %1}, %2;" : "=f"(f.x), "=f"(f.y) : "l"(v)); return f;
}
__device__ __forceinline__ void fma2(uint64_t& d, uint64_t a, uint64_t b) {
#if HAS_TCGEN05
    asm("fma.rn.f32x2 %0, %1, %2, %3;" : "=l"(d) : "l"(a), "l"(b), "l"(d));
#else
    float2 fd = unpack2(d), fa = unpack2(a), fb = unpack2(b);
    fd.x = fmaf(fa.x, fb.x, fd.x);
    fd.y = fmaf(fa.y, fb.y, fd.y);
    d = pack2(fd.x, fd.y);
#endif
}

// ---------------- ptx helpers ----------------
__device__ __forceinline__ uint32_t smem_u32(const void* p) {
    uint32_t a;
    asm("{ .reg .u64 t; cvta.to.shared.u64 t, %1; cvt.u32.u64 %0, t; }" : "=r"(a) : "l"(p));
    return a;
}
static __device__ __forceinline__ uint64_t make_desc(uint32_t addr) {
    const uint64_t base = (uint64_t(2) << 61) | (uint64_t(1) << 46) | (uint64_t(64) << 32) | (uint64_t(1) << 16);
    return base | ((uint64_t)(addr >> 4) & 0x3FFF);
}
__device__ __forceinline__ void mbar_init(uint32_t a, uint32_t cnt) {
    asm volatile("mbarrier.init.shared.b64 [%0], %1;" :: "r"(a), "r"(cnt) : "memory");
}
__device__ __forceinline__ void mbar_inval(uint32_t a) {
    asm volatile("mbarrier.inval.shared.b64 [%0];" :: "r"(a) : "memory");
}
__device__ __forceinline__ void mbar_wait(uint32_t a, uint32_t parity) {
    asm volatile(
        "{\n\t.reg .pred P1;\n\tWL_%=:\n\t"
        "mbarrier.try_wait.parity.acquire.cta.shared::cta.b64 P1, [%0], %1, 0x989680;\n\t"
        "@P1 bra.uni WD_%=;\n\tbra.uni WL_%=;\n\tWD_%=:\n\t}"
        :: "r"(a), "r"(parity) : "memory");
}
__device__ __forceinline__ void mbar_expect_tx(uint32_t a, uint32_t bytes) {
    asm volatile("mbarrier.arrive.expect_tx.shared.b64 _, [%0], %1;"
                 :: "r"(a), "r"(bytes) : "memory");
}
__device__ __forceinline__ void bulk_g2s(uint32_t dst, const void* src, uint32_t bytes, uint32_t mbar) {
    asm volatile("cp.async.bulk.shared::cta.global.mbarrier::complete_tx::bytes [%0], [%1], %2, [%3];"
                 :: "r"(dst), "l"(src), "r"(bytes), "r"(mbar) : "memory");
}

#if HAS_TCGEN05
__device__ __forceinline__ void mma_bf16_ss(uint32_t d, uint64_t ad, uint64_t bd, uint32_t idesc, uint32_t en) {
    asm volatile(
        "{\n\t.reg .pred p;\n\tsetp.ne.u32 p, %4, 0;\n\t"
        "tcgen05.mma.cta_group::1.kind::f16 [%0], %1, %2, %3, {%5, %5, %5, %5}, p;\n\t}"
        :: "r"(d), "l"(ad), "l"(bd), "r"(idesc), "r"(en), "r"(0u) : "memory");
}
__device__ __forceinline__ void tc_commit(uint32_t mbar) {
    asm volatile("tcgen05.commit.cta_group::1.mbarrier::arrive::one.shared::cluster.b64 [%0];"
                 :: "r"(mbar) : "memory");
}
#define TC_ALLOC(sa, n)  asm volatile("tcgen05.alloc.cta_group::1.sync.aligned.shared::cta.b32 [%0], %1;" :: "r"(sa), "r"(n) : "memory")
#define TC_DEALLOC(t, n) asm volatile("tcgen05.dealloc.cta_group::1.sync.aligned.b32 %0, %1;" :: "r"(t), "r"(n))
#define TC_FENCE_AFTER()  asm volatile("tcgen05.fence::after_thread_sync;" ::: "memory")
#define TC_FENCE_BEFORE() asm volatile("tcgen05.fence::before_thread_sync;" ::: "memory")
#define TC_WAIT_LD() asm volatile("tcgen05.wait::ld.sync.aligned;" ::: "memory")
#define LDTM_X32(r, a) \
    asm volatile("tcgen05.ld.sync.aligned.32x32b.x32.b32 " \
        "{%0, %1, %2, %3, %4, %5, %6, %7, %8, %9, %10, %11, %12, %13, %14, %15, " \
        "%16, %17, %18, %19, %20, %21, %22, %23, %24, %25, %26, %27, %28, %29, %30, %31}, [%32];" \
        : "=r"((r)[0]), "=r"((r)[1]), "=r"((r)[2]), "=r"((r)[3]), "=r"((r)[4]), "=r"((r)[5]), "=r"((r)[6]), "=r"((r)[7]), \
          "=r"((r)[8]), "=r"((r)[9]), "=r"((r)[10]), "=r"((r)[11]), "=r"((r)[12]), "=r"((r)[13]), "=r"((r)[14]), "=r"((r)[15]), \
          "=r"((r)[16]), "=r"((r)[17]), "=r"((r)[18]), "=r"((r)[19]), "=r"((r)[20]), "=r"((r)[21]), "=r"((r)[22]), "=r"((r)[23]), \
          "=r"((r)[24]), "=r"((r)[25]), "=r"((r)[26]), "=r"((r)[27]), "=r"((r)[28]), "=r"((r)[29]), "=r"((r)[30]), "=r"((r)[31]) \
        : "r"(a))
#endif

// ---------------- K1 ----------------
__global__ void k1_partial(const float* __restrict__ x, const float* __restrict__ motion) {
    int bt = blockIdx.x, chunk = blockIdx.y;
    int c = threadIdx.x;
    const int RPC = NTOK / 8;
    int n0 = chunk * RPC;
    const float* xp = x + ((size_t)(bt * NTOK + n0)) * C_ + c;
    float s = 0.f;
    for (int r = 0; r < RPC; ++r) s += xp[(size_t)r * C_];
    g_part[(bt * 8 + chunk) * C_ + c] = s;

    __shared__ float sm[512];
    float m = 0.f;
    for (int r = c; r < RPC; r += 512) m += motion[bt * NTOK + n0 + r];
    sm[c] = m;
    __syncthreads();
    for (int off = 256; off > 0; off >>= 1) {
        if (c < off) sm[c] += sm[c + off];
        __syncthreads();
    }
    if (c == 0) g_partmm[bt * 8 + chunk] = sm[0];
}

// ---------------- K2 ----------------
__global__ void k2_final(const float* __restrict__ temb) {
    int bt = blockIdx.x, c = threadIdx.x;
    float s = 0.f;
    for (int j = 0; j < 8; ++j) s += g_part[(bt * 8 + j) * C_ + c];
    g_xtime[bt * C_ + c] = s * (1.f / NTOK) + temb[c];
    if (c == 0) {
        float m = 0.f;
        for (int j = 0; j < 8; ++j) m += g_partmm[bt * 8 + j];
        g_mm[bt] = m * (1.f / NTOK);
    }
}

// ---------------- K3 ----------------
__global__ void k3_vecmat(const float* __restrict__ W, int mode) {
    int bt = blockIdx.x;
    int col = blockIdx.y * 256 + threadIdx.x;
    __shared__ float v[C_];
    for (int i = threadIdx.x; i < C_; i += 256) v[i] = g_xtime[bt * C_ + i];
    __syncthreads();
    float s = 0.f;
    #pragma unroll 8
    for (int c = 0; c < C_; ++c) s += v[c] * W[(size_t)c * C3 + col];
    float* dst = mode ? g_bias : g_qkvt;
    dst[bt * C3 + col] = s;
}

// ---------------- K4 ----------------
__global__ void k4_temporal() {
    int b = blockIdx.x, h = blockIdx.y, e = threadIdx.x;
    __shared__ float q[T_][DH], k[T_][DH], v[T_][DH];
    __shared__ float kvs[DH][DH + 1], ks[DH], mw[T_];
    for (int t = 0; t < T_; ++t) {
        int base = (b * T_ + t) * C3 + h * DH + e;
        q[t][e] = g_qkvt[base];
        k[t][e] = g_qkvt[base + C_];
        v[t][e] = g_qkvt[base + 2 * C_];
    }
    if (e < T_) mw[e] = 1.f + tanhf(g_mm[b * T_ + e]);
    __syncthreads();
    for (int t = 0; t < T_; ++t) {
        q[t][e] = phi(q[t][e]) * mw[t];
        k[t][e] = phi(k[t][e]);
    }
    __syncthreads();
    {
        float s = 0.f;
        for (int t = 0; t < T_; ++t) s += k[t][e];
        ks[e] = s;
    }
    for (int d = 0; d < DH; ++d) {
        float s = 0.f;
        for (int t = 0; t < T_; ++t) s += k[t][d] * v[t][e];
        kvs[d][e] = s;
    }
    __syncthreads();
    for (int t = 0; t < T_; ++t) {
        float den = 0.f, o = 0.f;
        #pragma unroll
        for (int d = 0; d < DH; ++d) {
            float qd = q[t][d];
            den += qd * ks[d];
            o   += qd * kvs[d][e];
        }
        float z = 1.f / (den + EPS);
        g_tout[(b * T_ + t) * C_ + h * DH + e] = o * z;
    }
}

// ---------------- K5 ----------------
__global__ void k5_prep(const float* __restrict__ temb) {
    int bt = blockIdx.x, c = threadIdx.x;
    g_xtime[bt * C_ + c] = temb[c] + g_tout[bt * C_ + c];
}

// ---------------- KA ----------------
__global__ void kA_split(const float* __restrict__ x) {
    size_t idx = (size_t)blockIdx.x * 256 + threadIdx.x;
    size_t row = idx >> 7;
    int q = (int)(idx & 127);
    float4 v = *(const float4*)(x + (row << 9) + q * 4);
    float f[4] = {v.x, v.y, v.z, v.w};
    uint32_t ph[2], pl[2];
    #pragma unroll
    for (int p = 0; p < 2; ++p) {
        __nv_bfloat16 h0 = __float2bfloat16_rn(f[2 * p]);
        __nv_bfloat16 h1 = __float2bfloat16_rn(f[2 * p + 1]);
        __nv_bfloat16 l0 = __float2bfloat16_rn(f[2 * p] - __bfloat162float(h0));
        __nv_bfloat16 l1 = __float2bfloat16_rn(f[2 * p + 1] - __bfloat162float(h1));
        ph[p] = (uint32_t)__bfloat16_as_ushort(h0) | ((uint32_t)__bfloat16_as_ushort(h1) << 16);
        pl[p] = (uint32_t)__bfloat16_as_ushort(l0) | ((uint32_t)__bfloat16_as_ushort(l1) << 16);
    }
    uint2 hv = {ph[0], ph[1]}, lv = {pl[0], pl[1]};

    int bm2 = (int)(row >> 8);
    int lr  = (int)(row & 255);
    int ch  = q >> 4;
    uint32_t off = (uint32_t)lr * 128 + (uint32_t)(q & 15) * 8;
    uint32_t so = off ^ ((off >> 3) & 0x70);
    char* hiDst = (char*)g_At + ((size_t)(bm2 * 16 + ch)) * AT_B + so;
    *(uint2*)hiDst = hv;
    *(uint2*)(hiDst + 8 * AT_B) = lv;
}

// ---------------- KB: head-paired B layout ----------------
__global__ void kB_build(const float* __restrict__ W) {
    int n = blockIdx.x * 256 + threadIdx.x;
    int k = blockIdx.y;
    float w = W[(size_t)k * C3 + n];
    __nv_bfloat16 hi = __float2bfloat16_rn(w);
    __nv_bfloat16 lo = __float2bfloat16_rn(w - __bfloat162float(hi));
    int np;
    if (n < 512) np = n;
    else if (n < 1024) { int h = (n - 512) >> 6; np = 512 + 128 * h + ((n - 512) & 63); }
    else               { int h = (n - 1024) >> 6; np = 512 + 128 * h + 64 + ((n - 1024) & 63); }
    int bn = np >> 8, rt = np & 255, ch = k >> 6, col = k & 63;
    uint32_t off = (uint32_t)rt * 128 + (uint32_t)col * 2;
    uint32_t so = off ^ ((off >> 3) & 0x70);
    char* dst = (char*)g_Bt + ((size_t)(bn * 16 + ch)) * BT_B + so;
    *(__nv_bfloat16*)dst = hi;
    *(__nv_bfloat16*)(dst + 8 * BT_B) = lo;
}

// ---------------- shared smem map ----------------
#define SM_TPTR 196608
#define SM_FULL 196616
#define SM_DONE 196640
#define SM_BIAS 196672      // 256 floats -> 197696
#define SM_SZ_KV 197696
// k6q extra:
#define SM_KSH2 197696      // 4*32 uint64 ksum pairs -> 198720
#define SM_KV2  198720      // 16 KB kv pairs -> 215104
#define SM_SZ_Q 215104
#define PSTR    260         // ps row stride in floats (1040 B, 16B aligned)

// ================= K6KV: GEMM + partial kv epilogue (bn 2..5) =================
__global__ void __launch_bounds__(256, 1) k6kv_mma() {
#if HAS_TCGEN05
    extern __shared__ char smem[];
    uint32_t sb = smem_u32(smem);
    int tid = threadIdx.x;
    int bn = blockIdx.x + 2, bm2 = blockIdx.y;
    int rowBase = bm2 * TM;
    int bt = rowBase / NTOK;

    {
        float* bias_s = (float*)(smem + SM_BIAS);
        for (int c = tid; c < TN; c += 256) {
            int hh = c >> 7, local = c & 127;
            int h = (bn - 2) * 2 + hh;
            int orig = (local < 64) ? (C_ + 64 * h + local) : (2 * C_ + 64 * h + (local - 64));
            bias_s[c] = g_bias[bt * C3 + orig];
        }
    }
    __syncthreads();

    if (tid < 32) TC_ALLOC(sb + SM_TPTR, 512);
    if (tid == 0) {
        #pragma unroll
        for (int s = 0; s < STAGES; ++s) {
            mbar_init(sb + SM_FULL + 8 * s, 1);
            mbar_init(sb + SM_DONE + 8 * s, 1);
        }
    }
    __syncthreads();
    uint32_t tmem;
    asm volatile("ld.shared.b32 %0, [%1];" : "=r"(tmem) : "r"(sb + SM_TPTR));

    const uint32_t idesc = (1u << 4) | (1u << 7) | (1u << 10) | (16u << 17) | (8u << 24);

    if (tid == 0) {
        const char* Abase = (const char*)g_At + (size_t)bm2 * 16 * AT_B;
        const char* Bbase = (const char*)g_Bt + (size_t)bn * 16 * BT_B;
        #pragma unroll
        for (int p = 0; p < 2; ++p) {
            uint32_t fullb = sb + SM_FULL + 8 * p;
            mbar_expect_tx(fullb, STG_B);
            bulk_g2s(sb + (uint32_t)p * STG_B,        Abase + (size_t)p * AT_B, AT_B, fullb);
            bulk_g2s(sb + (uint32_t)p * STG_B + AT_B, Bbase + (size_t)p * BT_B, BT_B, fullb);
        }
        for (int c = 0; c < NCHUNK; ++c) {
            int s = c % 3;
            mbar_wait(sb + SM_FULL + 8 * s, (c / 3) & 1);
            uint64_t ad0 = make_desc(sb + (uint32_t)s * STG_B);
            uint64_t ad1 = ad0 + 1024;
            uint64_t bd0 = make_desc(sb + (uint32_t)s * STG_B + AT_B);
            uint64_t bd1 = bd0 + 1024;
            #pragma unroll
            for (int ks = 0; ks < 4; ++ks) {
                uint32_t en = (c > 0 || ks > 0) ? 1u : 0u;
                mma_bf16_ss(tmem,       ad0 + 2 * ks, bd0 + 2 * ks, idesc, en);
                mma_bf16_ss(tmem + 128, ad0 + 2 * ks, bd1 + 2 * ks, idesc, en);
                mma_bf16_ss(tmem + 256, ad1 + 2 * ks, bd0 + 2 * ks, idesc, en);
                mma_bf16_ss(tmem + 384, ad1 + 2 * ks, bd1 + 2 * ks, idesc, en);
            }
            tc_commit(sb + SM_DONE + 8 * s);
            int pf = c + 2;
            if (pf < NCHUNK) {
                int sp = pf % 3;
                if (pf >= 3) mbar_wait(sb + SM_DONE + 8 * sp, ((pf - 3) / 3) & 1);
                int at = pf & 15;
                int btile = (pf < 8) ? pf : (pf - 8);
                uint32_t fullb = sb + SM_FULL + 8 * sp;
                mbar_expect_tx(fullb, STG_B);
                bulk_g2s(sb + (uint32_t)sp * STG_B,        Abase + (size_t)at * AT_B, AT_B, fullb);
                bulk_g2s(sb + (uint32_t)sp * STG_B + AT_B, Bbase + (size_t)btile * BT_B, BT_B, fullb);
            }
        }
        mbar_wait(sb + SM_DONE + 8 * 2, 1);
    }
    __syncthreads();
    TC_FENCE_AFTER();

    int lane = tid & 31, w = tid >> 5;
    int wi = w & 3, mh = w >> 2;
    float* ps = (float*)smem;                 // [256][132]
    const float* bias_s = (const float*)(smem + SM_BIAS);
    int tile = (rowBase - bt * NTOK) >> 8;
    int tok = mh * 128 + wi * 32 + lane;

    #pragma unroll
    for (int hh = 0; hh < 2; ++hh) {
        #pragma unroll
        for (int b = 0; b < 4; ++b) {
            uint32_t r[32];
            LDTM_X32(r, tmem + mh * 256 + hh * 128 + b * 32);
            TC_WAIT_LD();
            #pragma unroll
            for (int j = 0; j < 32; j += 4) {
                int cl = b * 32 + j;
                float4 o;
                o.x = __uint_as_float(r[j + 0]) + bias_s[hh * 128 + cl + 0];
                o.y = __uint_as_float(r[j + 1]) + bias_s[hh * 128 + cl + 1];
                o.z = __uint_as_float(r[j + 2]) + bias_s[hh * 128 + cl + 2];
                o.w = __uint_as_float(r[j + 3]) + bias_s[hh * 128 + cl + 3];
                if (cl < 64) { o.x = phi(o.x); o.y = phi(o.y); o.z = phi(o.z); o.w = phi(o.w); }
                *(float4*)(&ps[tok * 132 + cl]) = o;
            }
        }
        __syncthreads();

        int d4 = tid >> 4, e4 = tid & 15;
        uint64_t acc2[8];
        #pragma unroll
        for (int i = 0; i < 8; ++i) acc2[i] = pack2(0.f, 0.f);
        for (int n = 0; n < 256; ++n) {
            const float* row = &ps[n * 132];
            float4 kd = *(const float4*)(&row[d4 * 4]);
            uint64_t v0 = *(const uint64_t*)(&row[64 + e4 * 4]);
            uint64_t v1 = *(const uint64_t*)(&row[64 + e4 * 4 + 2]);
            uint64_t kx = pack2(kd.x, kd.x), ky = pack2(kd.y, kd.y);
            uint64_t kz = pack2(kd.z, kd.z), kw = pack2(kd.w, kd.w);
            fma2(acc2[0], kx, v0); fma2(acc2[1], kx, v1);
            fma2(acc2[2], ky, v0); fma2(acc2[3], ky, v1);
            fma2(acc2[4], kz, v0); fma2(acc2[5], kz, v1);
            fma2(acc2[6], kw, v0); fma2(acc2[7], kw, v1);
        }
        int h = (bn - 2) * 2 + hh;
        float* dst = g_kvp + ((size_t)((bt * NH + h) * NTILE + tile)) * (DH * DH);
        #pragma unroll
        for (int i = 0; i < 4; ++i) {
            float2 p0 = unpack2(acc2[i * 2]);
            float2 p1 = unpack2(acc2[i * 2 + 1]);
            float4 o = {p0.x, p0.y, p1.x, p1.y};
            *(float4*)(&dst[(d4 * 4 + i) * DH + e4 * 4]) = o;
        }
        if (tid < 64) {
            float s = 0.f;
            for (int n = 0; n < 256; ++n) s += ps[n * 132 + tid];
            g_ksump[((bt * NH + h) * NTILE + tile) * DH + tid] = s;
        }
        __syncthreads();
    }

    TC_FENCE_BEFORE();
    __syncthreads();
    if (tid == 0) {
        #pragma unroll
        for (int s = 0; s < STAGES; ++s) {
            mbar_inval(sb + SM_FULL + 8 * s);
            mbar_inval(sb + SM_DONE + 8 * s);
        }
    }
    __syncthreads();
    if (tid < 32) TC_DEALLOC(tmem, 512);
#else
    // fallback (compute_103 pass; never executed)
    int tid = threadIdx.x;
    int bn = blockIdx.x + 2, bm2 = blockIdx.y;
    int rowBase = bm2 * TM;
    int bt = rowBase / NTOK;
    auto gemm_elem = [&](int i, int j) {
        float s = 0.f;
        for (int kk = 0; kk < NCHUNK * TK; ++kk) {
            int c = kk >> 6, col = kk & 63;
            int at = c & 15;
            int btile = (c < 8) ? c : (c - 8);
            uint32_t ao = (uint32_t)i * 128 + col * 2; ao ^= ((ao >> 3) & 0x70);
            uint32_t bo = (uint32_t)j * 128 + col * 2; bo ^= ((bo >> 3) & 0x70);
            float a = __bfloat162float(*(const __nv_bfloat16*)((const char*)g_At + ((size_t)(bm2 * 16 + at)) * AT_B + ao));
            float b = __bfloat162float(*(const __nv_bfloat16*)((const char*)g_Bt + ((size_t)(bn * 16 + btile)) * BT_B + bo));
            s += a * b;
        }
        return s;
    };
    int tile = (rowBase - bt * NTOK) >> 8;
    for (int hh = 0; hh < 2; ++hh) {
        int h = (bn - 2) * 2 + hh;
        for (int de = tid; de < DH * DH; de += 256) {
            int d = de / DH, ee = de % DH;
            float acc = 0.f, ss = 0.f;
            for (int i = 0; i < TM; ++i) {
                float kb = g_bias[bt * C3 + C_ + 64 * h + d];
                float vb = g_bias[bt * C3 + 2 * C_ + 64 * h + ee];
                float pk = phi(gemm_elem(i, hh * 128 + d) + kb);
                float vv = gemm_elem(i, hh * 128 + 64 + ee) + vb;
                acc += pk * vv;
                if (ee == 0) ss += pk;
            }
            g_kvp[((size_t)((bt * NH + h) * NTILE + tile)) * (DH * DH) + d * DH + ee] = acc;
            if (ee == 0) g_ksump[((bt * NH + h) * NTILE + tile) * DH + d] = ss;
        }
    }
#endif
}

// ---------------- K7r: reduce 9 tile-partials ----------------
__global__ __launch_bounds__(256) void k7r_reduce() {
    int bh = blockIdx.x;
    int t = threadIdx.x;
    const float* src = g_kvp + (size_t)bh * NTILE * DH * DH;
    float* dst = g_kv + (size_t)bh * DH * DH;
    for (int i = t * 4; i < DH * DH; i += 256 * 4) {
        float4 a = {0.f, 0.f, 0.f, 0.f};
        #pragma unroll
        for (int p = 0; p < NTILE; ++p) {
            float4 s = *(const float4*)(src + (size_t)p * DH * DH + i);
            a.x += s.x; a.y += s.y; a.z += s.z; a.w += s.w;
        }
        *(float4*)(dst + i) = a;
    }
    if (t < DH) {
        const float* sp = g_ksump + bh * NTILE * DH;
        float s = 0.f;
        #pragma unroll
        for (int p = 0; p < NTILE; ++p) s += sp[p * DH + t];
        g_ksum[bh * DH + t] = s;
    }
}

// ================= K6Q: q GEMM + fused attention apply (bn 0..1) =================
__global__ void __launch_bounds__(256, 1) k6q_mma(const float* __restrict__ motion,
                                                  float* __restrict__ out) {
#if HAS_TCGEN05
    extern __shared__ char smem[];
    uint32_t sb = smem_u32(smem);
    int tid = threadIdx.x;
    int bn = blockIdx.x, bm2 = blockIdx.y;
    int rowBase = bm2 * TM, colBase = bn * TN;
    int bt = rowBase / NTOK;

    // q bias (orig layout) + ksum pairs
    ((float*)(smem + SM_BIAS))[tid] = g_bias[bt * C3 + colBase + tid];
    {   // ksh2[h*32+dp] = (ksum[2dp], ksum[2dp+1]) for 4 heads of this bn
        int hh = tid >> 6, r = tid & 63;   // r indexes 32 pairs x 2... use 128 threads
        if (tid < 128) {
            int dp = tid & 31; hh = tid >> 5;
            const float* kp = g_ksum + (size_t)(bt * NH + bn * 4 + hh) * DH;
            ((uint64_t*)(smem + SM_KSH2))[hh * 32 + dp] = pack2(kp[2 * dp], kp[2 * dp + 1]);
        }
        (void)r;
    }
    __syncthreads();

    if (tid < 32) TC_ALLOC(sb + SM_TPTR, 512);
    if (tid == 0) {
        #pragma unroll
        for (int s = 0; s < STAGES; ++s) {
            mbar_init(sb + SM_FULL + 8 * s, 1);
            mbar_init(sb + SM_DONE + 8 * s, 1);
        }
    }
    __syncthreads();
    uint32_t tmem;
    asm volatile("ld.shared.b32 %0, [%1];" : "=r"(tmem) : "r"(sb + SM_TPTR));

    const uint32_t idesc = (1u << 4) | (1u << 7) | (1u << 10) | (16u << 17) | (8u << 24);

    if (tid == 0) {
        const char* Abase = (const char*)g_At + (size_t)bm2 * 16 * AT_B;
        const char* Bbase = (const char*)g_Bt + (size_t)bn * 16 * BT_B;
        #pragma unroll
        for (int p = 0; p < 2; ++p) {
            uint32_t fullb = sb + SM_FULL + 8 * p;
            mbar_expect_tx(fullb, STG_B);
            bulk_g2s(sb + (uint32_t)p * STG_B,        Abase + (size_t)p * AT_B, AT_B, fullb);
            bulk_g2s(sb + (uint32_t)p * STG_B + AT_B, Bbase + (size_t)p * BT_B, BT_B, fullb);
        }
        for (int c = 0; c < NCHUNK; ++c) {
            int s = c % 3;
            mbar_wait(sb + SM_FULL + 8 * s, (c / 3) & 1);
            uint64_t ad0 = make_desc(sb + (uint32_t)s * STG_B);
            uint64_t ad1 = ad0 + 1024;
            uint64_t bd0 = make_desc(sb + (uint32_t)s * STG_B + AT_B);
            uint64_t bd1 = bd0 + 1024;
            #pragma unroll
            for (int ks = 0; ks < 4; ++ks) {
                uint32_t en = (c > 0 || ks > 0) ? 1u : 0u;
                mma_bf16_ss(tmem,       ad0 + 2 * ks, bd0 + 2 * ks, idesc, en);
                mma_bf16_ss(tmem + 128, ad0 + 2 * ks, bd1 + 2 * ks, idesc, en);
                mma_bf16_ss(tmem + 256, ad1 + 2 * ks, bd0 + 2 * ks, idesc, en);
                mma_bf16_ss(tmem + 384, ad1 + 2 * ks, bd1 + 2 * ks, idesc, en);
            }
            tc_commit(sb + SM_DONE + 8 * s);
            int pf = c + 2;
            if (pf < NCHUNK) {
                int sp = pf % 3;
                if (pf >= 3) mbar_wait(sb + SM_DONE + 8 * sp, ((pf - 3) / 3) & 1);
                int at = pf & 15;
                int btile = (pf < 8) ? pf : (pf - 8);
                uint32_t fullb = sb + SM_FULL + 8 * sp;
                mbar_expect_tx(fullb, STG_B);
                bulk_g2s(sb + (uint32_t)sp * STG_B,        Abase + (size_t)at * AT_B, AT_B, fullb);
                bulk_g2s(sb + (uint32_t)sp * STG_B + AT_B, Bbase + (size_t)btile * BT_B, BT_B, fullb);
            }
        }
        mbar_wait(sb + SM_DONE + 8 * 2, 1);
    }
    __syncthreads();
    TC_FENCE_AFTER();

    int lane = tid & 31, w = tid >> 5;
    int nbw = w >> 2, wi4 = w & 3;
    float* ps = (float*)smem;                          // [128][PSTR]
    const float* qbs = (const float*)(smem + SM_BIAS);
    const uint64_t* ksh2 = (const uint64_t*)(smem + SM_KSH2);
    uint64_t* kv2 = (uint64_t*)(smem + SM_KV2);

    for (int mhp = 0; mhp < 2; ++mhp) {
        __syncthreads();   // protect ps from previous readers
        // stage phi(q+bias)*mw for this 128-token half
        {
            int tok = wi4 * 32 + lane;
            int growf = rowBase - bt * NTOK + mhp * 128 + tok;   // row within frame
            float mm = motion[bt * NTOK + growf];
            float th;
            asm("tanh.approx.f32 %0, %1;" : "=f"(th) : "f"(mm));
            float mwv = 1.f + th;
            #pragma unroll
            for (int b = 0; b < 4; ++b) {
                uint32_t r[32];
                LDTM_X32(r, tmem + mhp * 256 + nbw * 128 + b * 32);
                TC_WAIT_LD();
                #pragma unroll
                for (int j = 0; j < 32; j += 4) {
                    int cl = nbw * 128 + b * 32 + j;
                    float4 o;
                    o.x = phi(__uint_as_float(r[j + 0]) + qbs[cl + 0]) * mwv;
                    o.y = phi(__uint_as_float(r[j + 1]) + qbs[cl + 1]) * mwv;
                    o.z = phi(__uint_as_float(r[j + 2]) + qbs[cl + 2]) * mwv;
                    o.w = phi(__uint_as_float(r[j + 3]) + qbs[cl + 3]) * mwv;
                    *(float4*)(&ps[tok * PSTR + cl]) = o;
                }
            }
        }
        __syncthreads();

        int tk = tid & 127;          // token in half
        int eh = tid >> 7;           // e-half: 0 -> e 0..31, 1 -> e 32..63
        for (int hh = 0; hh < 4; ++hh) {
            // load kv pairs for head h = bn*4+hh: kv2[dp*64+e] = (kv[2dp][e], kv[2dp+1][e])
            {
                const float* kvg = g_kv + (size_t)(bt * NH + bn * 4 + hh) * DH * DH;
                for (int i = tid; i < (DH / 2) * DH; i += 256) {
                    int dp = i >> 6, e2 = i & 63;
                    kv2[i] = pack2(kvg[(2 * dp) * DH + e2], kvg[(2 * dp + 1) * DH + e2]);
                }
            }
            __syncthreads();

            const uint64_t* qrow = (const uint64_t*)(ps + tk * PSTR + hh * 64);
            uint64_t den2 = pack2(0.f, 0.f);
            uint64_t acc2[32];
            #pragma unroll
            for (int i = 0; i < 32; ++i) acc2[i] = pack2(0.f, 0.f);
            for (int dp = 0; dp < 32; ++dp) {
                uint64_t q2 = qrow[dp];
                fma2(den2, q2, ksh2[hh * 32 + dp]);
                const uint64_t* kvrow = &kv2[dp * 64 + eh * 32];
                #pragma unroll
                for (int j = 0; j < 32; ++j)
                    fma2(acc2[j], q2, kvrow[j]);
            }
            float2 dd = unpack2(den2);
            float inv = 1.f / (dd.x + dd.y + EPS);
            int grow = rowBase + mhp * 128 + tk;
            float* op = out + (size_t)grow * C_ + (bn * 4 + hh) * DH + eh * 32;
            #pragma unroll
            for (int j = 0; j < 32; j += 4) {
                float2 a0 = unpack2(acc2[j]);
                float2 a1 = unpack2(acc2[j + 1]);
                float2 a2 = unpack2(acc2[j + 2]);
                float2 a3 = unpack2(acc2[j + 3]);
                float4 o = {(a0.x + a0.y) * inv, (a1.x + a1.y) * inv,
                            (a2.x + a2.y) * inv, (a3.x + a3.y) * inv};
                *(float4*)(op + j) = o;
            }
            __syncthreads();   // before kv2 reload
        }
    }

    TC_FENCE_BEFORE();
    __syncthreads();
    if (tid == 0) {
        #pragma unroll
        for (int s = 0; s < STAGES; ++s) {
            mbar_inval(sb + SM_FULL + 8 * s);
            mbar_inval(sb + SM_DONE + 8 * s);
        }
    }
    __syncthreads();
    if (tid < 32) TC_DEALLOC(tmem, 512);
#else
    // fallback (compute_103 pass; never executed): direct slow computation
    int tid = threadIdx.x;
    int bn = blockIdx.x, bm2 = blockIdx.y;
    int rowBase = bm2 * TM;
    int bt = rowBase / NTOK;
    auto gemm_elem = [&](int i, int j) {
        float s = 0.f;
        for (int kk = 0; kk < NCHUNK * TK; ++kk) {
            int c = kk >> 6, col = kk & 63;
            int at = c & 15;
            int btile = (c < 8) ? c : (c - 8);
            uint32_t ao = (uint32_t)i * 128 + col * 2; ao ^= ((ao >> 3) & 0x70);
            uint32_t bo = (uint32_t)j * 128 + col * 2; bo ^= ((bo >> 3) & 0x70);
            float a = __bfloat162float(*(const __nv_bfloat16*)((const char*)g_At + ((size_t)(bm2 * 16 + at)) * AT_B + ao));
            float b = __bfloat162float(*(const __nv_bfloat16*)((const char*)g_Bt + ((size_t)(bn * 16 + btile)) * BT_B + bo));
            s += a * b;
        }
        return s;
    };
    for (int i = tid; i < TM; i += 256) {
        int grow = rowBase + i;
        int growf = grow - bt * NTOK;
        float mw = 1.f + tanhf(motion[bt * NTOK + growf]);
        for (int hh = 0; hh < 4; ++hh) {
            int h = bn * 4 + hh;
            float qv[DH];
            float den = 0.f;
            for (int d = 0; d < DH; ++d) {
                qv[d] = phi(gemm_elem(i, hh * 64 + d) + g_bias[bt * C3 + h * 64 + d]) * mw;
                den += qv[d] * g_ksum[(bt * NH + h) * DH + d];
            }
            float inv = 1.f / (den + EPS);
            for (int e = 0; e < DH; ++e) {
                float o = 0.f;
                for (int d = 0; d < DH; ++d)
                    o += qv[d] * g_kv[(size_t)(bt * NH + h) * DH * DH + d * DH + e];
                out[(size_t)grow * C_ + h * DH + e] = o * inv;
            }
        }
    }
#endif
}

// ---------------- launch ----------------
extern "C" void kernel_launch(void* const* d_in, const int* in_sizes, int n_in,
                              void* d_out, int out_size) {
    const float* x      = (const float*)d_in[0];
    const float* motion = (const float*)d_in[1];
    const float* W      = (const float*)d_in[2];
    const float* temb   = (const float*)d_in[3];
    float* out = (float*)d_out;

    cudaFuncSetAttribute(k6kv_mma, cudaFuncAttributeMaxDynamicSharedMemorySize, SM_SZ_KV);
    cudaFuncSetAttribute(k6q_mma,  cudaFuncAttributeMaxDynamicSharedMemorySize, SM_SZ_Q);

    kA_split<<<(int)(((size_t)M_ * 128) / 256), 256>>>(x);
    kB_build<<<dim3(C3 / 256, C_), 256>>>(W);
    k1_partial<<<dim3(BT, 8), 512>>>(x, motion);
    k2_final<<<BT, 512>>>(temb);
    k3_vecmat<<<dim3(BT, 6), 256>>>(W, 0);
    k4_temporal<<<dim3(B_, NH), 64>>>();
    k5_prep<<<BT, 512>>>(temb);
    k3_vecmat<<<dim3(BT, 6), 256>>>(W, 1);
    k6kv_mma<<<dim3(4, NBM2), 256, SM_SZ_KV>>>();
    k7r_reduce<<<BT * NH, 256>>>();
    k6q_mma<<<dim3(2, NBM2), 256, SM_SZ_Q>>>(motion, out);
}